// round 7
// baseline (speedup 1.0000x reference)
#include <cuda_runtime.h>
#include <cuda_bf16.h>
#include <math.h>
#include <stdint.h>

#define SEQ    2048
#define DIM    4096
#define NH     32
#define NKV    8
#define HD     128
#define KVDIM  (NKV*HD)

// ---------------------------------------------------------------------------
// Scratch (device globals)
// ---------------------------------------------------------------------------
static __device__ float g_q[SEQ * DIM];
static __device__ float g_k[SEQ * KVDIM];
static __device__ float g_v[SEQ * KVDIM];
static __device__ float g_y[SEQ * DIM];

// int8 two-level operands + per-row scales
static __device__ int8_t g_xa1[SEQ * DIM],    g_xa2[SEQ * DIM];
static __device__ int8_t g_wqa1[DIM * DIM],   g_wqa2[DIM * DIM];
static __device__ int8_t g_wka1[KVDIM * DIM], g_wka2[KVDIM * DIM];
static __device__ int8_t g_wva1[KVDIM * DIM], g_wva2[KVDIM * DIM];
static __device__ int8_t g_woa1[DIM * DIM],   g_woa2[DIM * DIM];
static __device__ int8_t g_ya1[SEQ * DIM],    g_ya2[SEQ * DIM];
static __device__ float  g_sx[SEQ], g_swq[DIM], g_swk[KVDIM], g_swv[KVDIM],
                         g_swo[DIM], g_sy[SEQ];

// attention bf16 split operands
static __device__ __nv_bfloat16 g_qh[SEQ * DIM],    g_ql[SEQ * DIM];
static __device__ __nv_bfloat16 g_kh[SEQ * KVDIM],  g_kl[SEQ * KVDIM];
static __device__ __nv_bfloat16 g_vth[KVDIM * SEQ], g_vtl[KVDIM * SEQ];

// ---------------------------------------------------------------------------
// Helpers
// ---------------------------------------------------------------------------
__device__ __forceinline__ uint32_t smem_u32(const void* p) {
    uint32_t a;
    asm("{ .reg .u64 t; cvta.to.shared.u64 t, %1; cvt.u32.u64 %0, t; }"
        : "=r"(a) : "l"(p));
    return a;
}

__device__ __forceinline__ void ldsm_x4(uint32_t* d, uint32_t addr) {
    asm volatile("ldmatrix.sync.aligned.m8n8.x4.shared.b16 {%0,%1,%2,%3}, [%4];"
                 : "=r"(d[0]), "=r"(d[1]), "=r"(d[2]), "=r"(d[3]) : "r"(addr));
}

__device__ __forceinline__ void mma16816(float* c, const uint32_t* a,
                                         uint32_t b0, uint32_t b1) {
    asm volatile(
        "mma.sync.aligned.m16n8k16.row.col.f32.bf16.bf16.f32 "
        "{%0,%1,%2,%3}, {%4,%5,%6,%7}, {%8,%9}, {%0,%1,%2,%3};"
        : "+f"(c[0]), "+f"(c[1]), "+f"(c[2]), "+f"(c[3])
        : "r"(a[0]), "r"(a[1]), "r"(a[2]), "r"(a[3]), "r"(b0), "r"(b1));
}

__device__ __forceinline__ void imma16832(int* c, const uint32_t* a,
                                          uint32_t b0, uint32_t b1) {
    asm volatile(
        "mma.sync.aligned.m16n8k32.row.col.s32.s8.s8.s32 "
        "{%0,%1,%2,%3}, {%4,%5,%6,%7}, {%8,%9}, {%0,%1,%2,%3};"
        : "+r"(c[0]), "+r"(c[1]), "+r"(c[2]), "+r"(c[3])
        : "r"(a[0]), "r"(a[1]), "r"(a[2]), "r"(a[3]), "r"(b0), "r"(b1));
}

#define CP_ASYNC16(dst, src) \
    asm volatile("cp.async.cg.shared.global [%0], [%1], 16;" :: "r"(dst), "l"(src))
#define CP_COMMIT() asm volatile("cp.async.commit_group;" ::: "memory")
#define CP_WAIT0()  asm volatile("cp.async.wait_group 0;"  ::: "memory")
#define CP_WAIT1()  asm volatile("cp.async.wait_group 1;"  ::: "memory")

__device__ __forceinline__ void split2(float a, __nv_bfloat16& h, __nv_bfloat16& l) {
    h = __float2bfloat16(a);
    l = __float2bfloat16(a - __bfloat162float(h));
}

// ---------------------------------------------------------------------------
// Two-level int8 quantization, per row of K=4096.
// x ~= s*a1 + (s/250)*a2,  |a1|<=127, |a2|<=126, err <= s/500.
// ---------------------------------------------------------------------------
__global__ void __launch_bounds__(256) quant_kernel(
    const float* __restrict__ in, int8_t* __restrict__ q1,
    int8_t* __restrict__ q2, float* __restrict__ scale, int K)
{
    const int row = blockIdx.x;
    const int tid = threadIdx.x;
    const float* src = in + (size_t)row * K;
    const float4* s4 = (const float4*)src;

    float mx = 0.f;
    for (int i = tid; i < K / 4; i += 256) {
        float4 v = s4[i];
        mx = fmaxf(mx, fmaxf(fmaxf(fabsf(v.x), fabsf(v.y)),
                             fmaxf(fabsf(v.z), fabsf(v.w))));
    }
#pragma unroll
    for (int o = 16; o; o >>= 1) mx = fmaxf(mx, __shfl_xor_sync(~0u, mx, o));
    __shared__ float smx[8];
    if ((tid & 31) == 0) smx[tid >> 5] = mx;
    __syncthreads();
    float bm = 0.f;
#pragma unroll
    for (int i = 0; i < 8; i++) bm = fmaxf(bm, smx[i]);
    const float s = (bm > 0.f) ? bm / 127.f : 1.f;
    const float inv = 1.f / s;
    const float inv250 = 250.f * inv;
    if (tid == 0) scale[row] = s;

    for (int i = tid; i < K / 16; i += 256) {
        union { int8_t b[16]; uint4 u; } p1, p2;
#pragma unroll
        for (int j = 0; j < 4; j++) {
            float4 v = s4[i * 4 + j];
            float vv[4] = {v.x, v.y, v.z, v.w};
#pragma unroll
            for (int e = 0; e < 4; e++) {
                int a = __float2int_rn(vv[e] * inv);
                float r = fmaf(-s, (float)a, vv[e]);
                p1.b[j * 4 + e] = (int8_t)a;
                p2.b[j * 4 + e] = (int8_t)__float2int_rn(r * inv250);
            }
        }
        ((uint4*)(q1 + (size_t)row * K))[i] = p1.u;
        ((uint4*)(q2 + (size_t)row * K))[i] = p2.u;
    }
}

// ---------------------------------------------------------------------------
// RoPE + scale + split (attention operands)
// ---------------------------------------------------------------------------
__global__ void rope_split_kernel(const float* __restrict__ x,
                                  const float* __restrict__ fc,
                                  __nv_bfloat16* __restrict__ oh,
                                  __nv_bfloat16* __restrict__ ol,
                                  int nheads, float scale, int total)
{
    int idx = blockIdx.x * blockDim.x + threadIdx.x;
    if (idx >= total) return;
    const int i = idx & 63;
    const int h = (idx >> 6) % nheads;
    const int s = idx / (64 * nheads);
    const float c  = fc[(s * 64 + i) * 2 + 0];
    const float sn = fc[(s * 64 + i) * 2 + 1];
    const size_t off = ((size_t)s * nheads + h) * HD + 2 * i;
    float2 v = *(const float2*)(x + off);
    float a = (v.x * c - v.y * sn) * scale;
    float b = (v.y * c + v.x * sn) * scale;
    __nv_bfloat16 ah, al, bh, bl;
    split2(a, ah, al); split2(b, bh, bl);
    *(__nv_bfloat162*)(oh + off) = __nv_bfloat162(ah, bh);
    *(__nv_bfloat162*)(ol + off) = __nv_bfloat162(al, bl);
}

__global__ void split_vt_kernel(const float* __restrict__ v,
                                __nv_bfloat16* __restrict__ vh,
                                __nv_bfloat16* __restrict__ vl)
{
    int idx = blockIdx.x * blockDim.x + threadIdx.x;
    const int s = idx & (SEQ - 1);
    const int dl = idx >> 11;
    if (dl >= KVDIM) return;
    float val = v[(size_t)s * KVDIM + dl];
    __nv_bfloat16 h, l;
    split2(val, h, l);
    vh[idx] = h; vl[idx] = l;
}

// ---------------------------------------------------------------------------
// INT8 IMMA GEMM. CTA tile 128x128, 8 warps (2x4), warp tile 64x32.
// K-chunk 128 int8 (128B rows), 3-stage cp.async.
// Stage 64KB: A1 16K | A2 16K | B1 16K | B2 16K.
// ---------------------------------------------------------------------------
#define I8_STAGE 65536
#define I8_SMEM  (3 * I8_STAGE + 1024)
#define I8_NC    (DIM / 128)

__device__ __forceinline__ void i8_stage_load(
    uint32_t st, const int8_t* __restrict__ A1, const int8_t* __restrict__ A2,
    const int8_t* __restrict__ B1, const int8_t* __restrict__ B2,
    int row0, int col0, int k0, int tid)
{
    const int r = tid >> 1, h = tid & 1, sw = r & 7;
    const size_t aoff = (size_t)(row0 + r) * DIM + k0 + h * 64;
    const size_t boff = (size_t)(col0 + r) * DIM + k0 + h * 64;
#pragma unroll
    for (int u = 0; u < 4; u++) {
        const int phys = (((h * 4 + u) ^ sw) * 16);
        CP_ASYNC16(st + 0     + r * 128 + phys, A1 + aoff + u * 16);
        CP_ASYNC16(st + 16384 + r * 128 + phys, A2 + aoff + u * 16);
        CP_ASYNC16(st + 32768 + r * 128 + phys, B1 + boff + u * 16);
        CP_ASYNC16(st + 49152 + r * 128 + phys, B2 + boff + u * 16);
    }
}

__device__ __forceinline__ void i8_gemm_body(
    const int8_t* __restrict__ A1, const int8_t* __restrict__ A2,
    const int8_t* __restrict__ B1, const int8_t* __restrict__ B2,
    const float* __restrict__ sA, const float* __restrict__ sB,
    float* __restrict__ C, int Ntot, int row0, int col0, char* smraw)
{
    const uint32_t sbase = (smem_u32(smraw) + 1023u) & ~1023u;
    const int tid = threadIdx.x;
    const int lid = tid & 31;
    const int wid = tid >> 5;
    const int wm  = wid & 1;
    const int wn  = wid >> 1;

    int s1[4][4][4], s2[4][4][4];
#pragma unroll
    for (int i = 0; i < 4; i++)
#pragma unroll
        for (int j = 0; j < 4; j++)
#pragma unroll
            for (int q = 0; q < 4; q++) { s1[i][j][q] = 0; s2[i][j][q] = 0; }

    i8_stage_load(sbase,            A1, A2, B1, B2, row0, col0, 0,   tid);
    CP_COMMIT();
    i8_stage_load(sbase + I8_STAGE, A1, A2, B1, B2, row0, col0, 128, tid);
    CP_COMMIT();

    int cur = 0, nxt = 2;
    for (int c = 0; c < I8_NC; c++) {
        CP_WAIT1();
        __syncthreads();
        if (c + 2 < I8_NC) {
            i8_stage_load(sbase + nxt * I8_STAGE,
                          A1, A2, B1, B2, row0, col0, (c + 2) * 128, tid);
            CP_COMMIT();
        }
        const uint32_t a1b = sbase + cur * I8_STAGE;
        const uint32_t a2b = a1b + 16384;
        const uint32_t b1b = a1b + 32768;
        const uint32_t b2b = a1b + 49152;
        cur = (cur == 2) ? 0 : cur + 1;
        nxt = (nxt == 2) ? 0 : nxt + 1;

#pragma unroll
        for (int kc = 0; kc < 4; kc++) {
            uint32_t a1f[4][4], a2f[4][4], b1f[2][4], b2f[2][4];
#pragma unroll
            for (int mt = 0; mt < 4; mt++) {
                const int rA = wm * 64 + mt * 16 + (lid & 15);
                const int uA = kc * 2 + (lid >> 4);
                const uint32_t off = rA * 128 + ((uA ^ (rA & 7)) * 16);
                ldsm_x4(a1f[mt], a1b + off);
                ldsm_x4(a2f[mt], a2b + off);
            }
#pragma unroll
            for (int np = 0; np < 2; np++) {
                const int rB = wn * 32 + np * 16 + ((lid >> 4) & 1) * 8 + (lid & 7);
                const int uB = kc * 2 + ((lid >> 3) & 1);
                const uint32_t off = rB * 128 + ((uB ^ (rB & 7)) * 16);
                ldsm_x4(b1f[np], b1b + off);
                ldsm_x4(b2f[np], b2b + off);
            }
#pragma unroll
            for (int mt = 0; mt < 4; mt++)
#pragma unroll
                for (int nt = 0; nt < 4; nt++) {
                    const uint32_t p0 = b1f[nt >> 1][(nt & 1) * 2];
                    const uint32_t p1 = b1f[nt >> 1][(nt & 1) * 2 + 1];
                    const uint32_t q0 = b2f[nt >> 1][(nt & 1) * 2];
                    const uint32_t q1 = b2f[nt >> 1][(nt & 1) * 2 + 1];
                    imma16832(s1[mt][nt], a1f[mt], p0, p1);
                    imma16832(s2[mt][nt], a1f[mt], q0, q1);
                    imma16832(s2[mt][nt], a2f[mt], p0, p1);
                }
        }
    }

    const float kk = 1.f / 250.f;
#pragma unroll
    for (int mt = 0; mt < 4; mt++) {
        const int r = row0 + wm * 64 + mt * 16 + (lid >> 2);
        const float sa0 = sA[r], sa1 = sA[r + 8];
#pragma unroll
        for (int nt = 0; nt < 4; nt++) {
            const int cc = col0 + wn * 32 + nt * 8 + (lid & 3) * 2;
            const float sb0 = sB[cc], sb1 = sB[cc + 1];
            C[(size_t)r * Ntot + cc] =
                sa0 * sb0 * ((float)s1[mt][nt][0] + (float)s2[mt][nt][0] * kk);
            C[(size_t)r * Ntot + cc + 1] =
                sa0 * sb1 * ((float)s1[mt][nt][1] + (float)s2[mt][nt][1] * kk);
            C[(size_t)(r + 8) * Ntot + cc] =
                sa1 * sb0 * ((float)s1[mt][nt][2] + (float)s2[mt][nt][2] * kk);
            C[(size_t)(r + 8) * Ntot + cc + 1] =
                sa1 * sb1 * ((float)s1[mt][nt][3] + (float)s2[mt][nt][3] * kk);
        }
    }
}

// Fused QKV: blockIdx.x 0..47 (0-31 Q, 32-39 K, 40-47 V), col blocks of 128.
__global__ void __launch_bounds__(256, 1)
gemm_i8_qkv(const int8_t* __restrict__ xa1, const int8_t* __restrict__ xa2,
            const float* __restrict__ sx,
            const int8_t* __restrict__ wqa1, const int8_t* __restrict__ wqa2,
            const float* __restrict__ swq,
            const int8_t* __restrict__ wka1, const int8_t* __restrict__ wka2,
            const float* __restrict__ swk,
            const int8_t* __restrict__ wva1, const int8_t* __restrict__ wva2,
            const float* __restrict__ swv,
            float* __restrict__ Q, float* __restrict__ K, float* __restrict__ V)
{
    extern __shared__ char smraw[];
    const int xb = blockIdx.x;
    const int row0 = blockIdx.y * 128;
    const int8_t *B1, *B2; const float* sB;
    float* C; int Ntot, col0;
    if (xb < 32)      { B1 = wqa1; B2 = wqa2; sB = swq; C = Q; Ntot = DIM;   col0 = xb * 128; }
    else if (xb < 40) { B1 = wka1; B2 = wka2; sB = swk; C = K; Ntot = KVDIM; col0 = (xb - 32) * 128; }
    else              { B1 = wva1; B2 = wva2; sB = swv; C = V; Ntot = KVDIM; col0 = (xb - 40) * 128; }
    i8_gemm_body(xa1, xa2, B1, B2, sx, sB, C, Ntot, row0, col0, smraw);
}

__global__ void __launch_bounds__(256, 1)
gemm_i8(const int8_t* __restrict__ A1, const int8_t* __restrict__ A2,
        const float* __restrict__ sA,
        const int8_t* __restrict__ B1, const int8_t* __restrict__ B2,
        const float* __restrict__ sB, float* __restrict__ C, int Ntot)
{
    extern __shared__ char smraw[];
    i8_gemm_body(A1, A2, B1, B2, sA, sB, C, Ntot,
                 blockIdx.y * 128, blockIdx.x * 128, smraw);
}

// ---------------------------------------------------------------------------
// HMMA flash attention (validated R6). Br=128, Bc=64, causal, GQA rep 4.
// ---------------------------------------------------------------------------
#define AT_QH 0
#define AT_QL 32768
#define AT_ST(b) (65536 + (b) * 65536)
#define AT_KH 0
#define AT_KL 16384
#define AT_VH 32768
#define AT_VL 49152
#define AT_SMEM (65536 + 2 * 65536)

__device__ __forceinline__ void attn_load_kv(
    uint32_t stage, const __nv_bfloat16* __restrict__ Kh,
    const __nv_bfloat16* __restrict__ Kl,
    const __nv_bfloat16* __restrict__ Vth, const __nv_bfloat16* __restrict__ Vtl,
    int j, int kvh, int tid)
{
    for (int idx = tid; idx < 1024; idx += 256) {
        const int r = idx >> 4, u = idx & 15;
        const int phys = ((u ^ (r & 7)) * 16);
        const size_t gk = ((size_t)(j * 64 + r) * NKV + kvh) * HD + u * 8;
        CP_ASYNC16(stage + AT_KH + r * 256 + phys, Kh + gk);
        CP_ASYNC16(stage + AT_KL + r * 256 + phys, Kl + gk);
    }
    for (int idx = tid; idx < 1024; idx += 256) {
        const int r = idx >> 3, u = idx & 7;
        const int phys = ((u ^ (r & 7)) * 16);
        const size_t gv = ((size_t)(kvh * 128 + r)) * SEQ + j * 64 + u * 8;
        CP_ASYNC16(stage + AT_VH + r * 128 + phys, Vth + gv);
        CP_ASYNC16(stage + AT_VL + r * 128 + phys, Vtl + gv);
    }
}

__global__ void __launch_bounds__(256, 1)
attn_hmma_kernel(const __nv_bfloat16* __restrict__ Qh,
                 const __nv_bfloat16* __restrict__ Ql,
                 const __nv_bfloat16* __restrict__ Kh,
                 const __nv_bfloat16* __restrict__ Kl,
                 const __nv_bfloat16* __restrict__ Vth,
                 const __nv_bfloat16* __restrict__ Vtl,
                 float* __restrict__ Y)
{
    extern __shared__ char smraw[];
    const uint32_t sb = smem_u32(smraw);

    const int qt  = blockIdx.x;
    const int h   = blockIdx.y;
    const int kvh = h >> 2;
    const int tid = threadIdx.x;
    const int lid = tid & 31;
    const int wid = tid >> 5;
    const int qrow0 = qt * 128;

    for (int idx = tid; idx < 2048; idx += 256) {
        const int r = idx >> 4, u = idx & 15;
        const int phys = ((u ^ (r & 7)) * 16);
        const size_t g = ((size_t)(qrow0 + r) * NH + h) * HD + u * 8;
        CP_ASYNC16(sb + AT_QH + r * 256 + phys, Qh + g);
        CP_ASYNC16(sb + AT_QL + r * 256 + phys, Ql + g);
    }
    attn_load_kv(sb + AT_ST(0), Kh, Kl, Vth, Vtl, 0, kvh, tid);
    CP_COMMIT();

    float o[16][4];
#pragma unroll
    for (int dt = 0; dt < 16; dt++)
#pragma unroll
        for (int q = 0; q < 4; q++) o[dt][q] = 0.f;
    float mA = -1e30f, mB = -1e30f, lA = 0.f, lB = 0.f;

    const int g  = lid >> 2;
    const int cA = (lid & 3) * 2;
    const int jEnd = 2 * qt + 1;

    for (int j = 0; j <= jEnd; j++) {
        CP_WAIT0();
        __syncthreads();
        if (j < jEnd) {
            attn_load_kv(sb + AT_ST((j + 1) & 1), Kh, Kl, Vth, Vtl, j + 1, kvh, tid);
            CP_COMMIT();
        }
        const uint32_t kb = sb + AT_ST(j & 1);

        float s[8][4];
#pragma unroll
        for (int nt = 0; nt < 8; nt++)
#pragma unroll
            for (int q = 0; q < 4; q++) s[nt][q] = 0.f;

#pragma unroll
        for (int kc = 0; kc < 8; kc++) {
            uint32_t qhf[4], qlf[4];
            const int rA = wid * 16 + (lid & 15);
            const int uA = kc * 2 + (lid >> 4);
            ldsm_x4(qhf, sb + AT_QH + rA * 256 + ((uA ^ (rA & 7)) * 16));
            ldsm_x4(qlf, sb + AT_QL + rA * 256 + ((uA ^ (rA & 7)) * 16));
#pragma unroll
            for (int np = 0; np < 4; np++) {
                uint32_t khf[4], klf[4];
                const int rB = np * 16 + ((lid >> 4) & 1) * 8 + (lid & 7);
                const int uB = kc * 2 + ((lid >> 3) & 1);
                ldsm_x4(khf, kb + AT_KH + rB * 256 + ((uB ^ (rB & 7)) * 16));
                ldsm_x4(klf, kb + AT_KL + rB * 256 + ((uB ^ (rB & 7)) * 16));
#pragma unroll
                for (int hf = 0; hf < 2; hf++) {
                    const int nt = np * 2 + hf;
                    mma16816(s[nt], qhf, khf[hf * 2], khf[hf * 2 + 1]);
                    mma16816(s[nt], qhf, klf[hf * 2], klf[hf * 2 + 1]);
                    mma16816(s[nt], qlf, khf[hf * 2], khf[hf * 2 + 1]);
                }
            }
        }

        if (j >= 2 * qt) {
            const int rowA = qrow0 + wid * 16 + g;
            const int colBase = j * 64;
#pragma unroll
            for (int nt = 0; nt < 8; nt++) {
                const int col = colBase + nt * 8 + cA;
                if (col     > rowA)     s[nt][0] = -1e30f;
                if (col + 1 > rowA)     s[nt][1] = -1e30f;
                if (col     > rowA + 8) s[nt][2] = -1e30f;
                if (col + 1 > rowA + 8) s[nt][3] = -1e30f;
            }
        }

        float mxA = -1e30f, mxB = -1e30f;
#pragma unroll
        for (int nt = 0; nt < 8; nt++) {
            mxA = fmaxf(mxA, fmaxf(s[nt][0], s[nt][1]));
            mxB = fmaxf(mxB, fmaxf(s[nt][2], s[nt][3]));
        }
        mxA = fmaxf(mxA, __shfl_xor_sync(0xffffffffu, mxA, 1));
        mxA = fmaxf(mxA, __shfl_xor_sync(0xffffffffu, mxA, 2));
        mxB = fmaxf(mxB, __shfl_xor_sync(0xffffffffu, mxB, 1));
        mxB = fmaxf(mxB, __shfl_xor_sync(0xffffffffu, mxB, 2));
        const float mnA = fmaxf(mA, mxA), mnB = fmaxf(mB, mxB);
        const float alA = __expf(mA - mnA), alB = __expf(mB - mnB);

        uint32_t ph[8][2], pl[8][2];
        float rsA = 0.f, rsB = 0.f;
#pragma unroll
        for (int nt = 0; nt < 8; nt++) {
            float p0 = __expf(s[nt][0] - mnA);
            float p1 = __expf(s[nt][1] - mnA);
            float p2 = __expf(s[nt][2] - mnB);
            float p3 = __expf(s[nt][3] - mnB);
            rsA += p0 + p1;  rsB += p2 + p3;
            __nv_bfloat16 h0, h1, h2, h3, e0, e1, e2, e3;
            split2(p0, h0, e0); split2(p1, h1, e1);
            split2(p2, h2, e2); split2(p3, h3, e3);
            __nv_bfloat162 a0(h0, h1), a1(h2, h3), b0(e0, e1), b1(e2, e3);
            ph[nt][0] = *reinterpret_cast<uint32_t*>(&a0);
            ph[nt][1] = *reinterpret_cast<uint32_t*>(&a1);
            pl[nt][0] = *reinterpret_cast<uint32_t*>(&b0);
            pl[nt][1] = *reinterpret_cast<uint32_t*>(&b1);
        }
        rsA += __shfl_xor_sync(0xffffffffu, rsA, 1);
        rsA += __shfl_xor_sync(0xffffffffu, rsA, 2);
        rsB += __shfl_xor_sync(0xffffffffu, rsB, 1);
        rsB += __shfl_xor_sync(0xffffffffu, rsB, 2);
        lA = lA * alA + rsA;  mA = mnA;
        lB = lB * alB + rsB;  mB = mnB;

#pragma unroll
        for (int dt = 0; dt < 16; dt++) {
            o[dt][0] *= alA; o[dt][1] *= alA;
            o[dt][2] *= alB; o[dt][3] *= alB;
        }

#pragma unroll
        for (int kc = 0; kc < 4; kc++) {
            uint32_t aH[4] = { ph[2 * kc][0], ph[2 * kc][1],
                               ph[2 * kc + 1][0], ph[2 * kc + 1][1] };
            uint32_t aL[4] = { pl[2 * kc][0], pl[2 * kc][1],
                               pl[2 * kc + 1][0], pl[2 * kc + 1][1] };
#pragma unroll
            for (int dp = 0; dp < 8; dp++) {
                uint32_t vhf[4], vlf[4];
                const int rB = dp * 16 + ((lid >> 4) & 1) * 8 + (lid & 7);
                const int uB = kc * 2 + ((lid >> 3) & 1);
                ldsm_x4(vhf, kb + AT_VH + rB * 128 + ((uB ^ (rB & 7)) * 16));
                ldsm_x4(vlf, kb + AT_VL + rB * 128 + ((uB ^ (rB & 7)) * 16));
#pragma unroll
                for (int hf = 0; hf < 2; hf++) {
                    const int dt = dp * 2 + hf;
                    mma16816(o[dt], aH, vhf[hf * 2], vhf[hf * 2 + 1]);
                    mma16816(o[dt], aL, vhf[hf * 2], vhf[hf * 2 + 1]);
                    mma16816(o[dt], aH, vlf[hf * 2], vlf[hf * 2 + 1]);
                }
            }
        }
    }

    const float invA = 1.f / lA, invB = 1.f / lB;
    const int rowA = qrow0 + wid * 16 + g;
#pragma unroll
    for (int dt = 0; dt < 16; dt++) {
        const int d = h * HD + dt * 8 + cA;
        *(float2*)&Y[(size_t)rowA * DIM + d] =
            make_float2(o[dt][0] * invA, o[dt][1] * invA);
        *(float2*)&Y[(size_t)(rowA + 8) * DIM + d] =
            make_float2(o[dt][2] * invB, o[dt][3] * invB);
    }
}

// ---------------------------------------------------------------------------
// Launch
// ---------------------------------------------------------------------------
extern "C" void kernel_launch(void* const* d_in, const int* in_sizes, int n_in,
                              void* d_out, int out_size)
{
    const float* x  = (const float*)d_in[0];
    const float* fc = (const float*)d_in[1];
    const float* wq = (const float*)d_in[3];
    const float* wk = (const float*)d_in[4];
    const float* wv = (const float*)d_in[5];
    const float* wo = (const float*)d_in[6];
    float* out = (float*)d_out;

    float *Q, *Kp, *Vp, *Yp;
    cudaGetSymbolAddress((void**)&Q,  g_q);
    cudaGetSymbolAddress((void**)&Kp, g_k);
    cudaGetSymbolAddress((void**)&Vp, g_v);
    cudaGetSymbolAddress((void**)&Yp, g_y);

    int8_t *xa1, *xa2, *wqa1, *wqa2, *wka1, *wka2, *wva1, *wva2, *woa1, *woa2, *ya1, *ya2;
    float *sx, *swq, *swk, *swv, *swo, *sy;
    cudaGetSymbolAddress((void**)&xa1, g_xa1);   cudaGetSymbolAddress((void**)&xa2, g_xa2);
    cudaGetSymbolAddress((void**)&wqa1, g_wqa1); cudaGetSymbolAddress((void**)&wqa2, g_wqa2);
    cudaGetSymbolAddress((void**)&wka1, g_wka1); cudaGetSymbolAddress((void**)&wka2, g_wka2);
    cudaGetSymbolAddress((void**)&wva1, g_wva1); cudaGetSymbolAddress((void**)&wva2, g_wva2);
    cudaGetSymbolAddress((void**)&woa1, g_woa1); cudaGetSymbolAddress((void**)&woa2, g_woa2);
    cudaGetSymbolAddress((void**)&ya1, g_ya1);   cudaGetSymbolAddress((void**)&ya2, g_ya2);
    cudaGetSymbolAddress((void**)&sx, g_sx);   cudaGetSymbolAddress((void**)&swq, g_swq);
    cudaGetSymbolAddress((void**)&swk, g_swk); cudaGetSymbolAddress((void**)&swv, g_swv);
    cudaGetSymbolAddress((void**)&swo, g_swo); cudaGetSymbolAddress((void**)&sy, g_sy);

    __nv_bfloat16 *qh, *ql, *kh, *kl, *vth, *vtl;
    cudaGetSymbolAddress((void**)&qh,  g_qh);  cudaGetSymbolAddress((void**)&ql,  g_ql);
    cudaGetSymbolAddress((void**)&kh,  g_kh);  cudaGetSymbolAddress((void**)&kl,  g_kl);
    cudaGetSymbolAddress((void**)&vth, g_vth); cudaGetSymbolAddress((void**)&vtl, g_vtl);

    cudaFuncSetAttribute(gemm_i8_qkv,
                         cudaFuncAttributeMaxDynamicSharedMemorySize, I8_SMEM);
    cudaFuncSetAttribute(gemm_i8,
                         cudaFuncAttributeMaxDynamicSharedMemorySize, I8_SMEM);
    cudaFuncSetAttribute(attn_hmma_kernel,
                         cudaFuncAttributeMaxDynamicSharedMemorySize, AT_SMEM);

    const int T = 256;
    // Quantize inputs + weights (per-row, two-level int8)
    quant_kernel<<<SEQ,   T>>>(x,  xa1, xa2, sx,  DIM);
    quant_kernel<<<DIM,   T>>>(wq, wqa1, wqa2, swq, DIM);
    quant_kernel<<<KVDIM, T>>>(wk, wka1, wka2, swk, DIM);
    quant_kernel<<<KVDIM, T>>>(wv, wva1, wva2, swv, DIM);
    quant_kernel<<<DIM,   T>>>(wo, woa1, woa2, swo, DIM);

    // Fused QKV projection (int8 IMMA)
    gemm_i8_qkv<<<dim3(48, SEQ / 128), 256, I8_SMEM>>>(
        xa1, xa2, sx, wqa1, wqa2, swq, wka1, wka2, swk, wva1, wva2, swv,
        Q, Kp, Vp);

    // RoPE + split (attention bf16 operands); V transpose + split
    const float scale = 0.08838834764831845f;
    rope_split_kernel<<<(SEQ * NH  * 64 + T - 1) / T, T>>>(
        Q,  fc, qh, ql, NH,  scale, SEQ * NH  * 64);
    rope_split_kernel<<<(SEQ * NKV * 64 + T - 1) / T, T>>>(
        Kp, fc, kh, kl, NKV, 1.0f,  SEQ * NKV * 64);
    split_vt_kernel<<<(KVDIM * SEQ + T - 1) / T, T>>>(Vp, vth, vtl);

    // Attention (split-bf16 HMMA, Br=128)
    attn_hmma_kernel<<<dim3(SEQ / 128, NH), 256, AT_SMEM>>>(
        qh, ql, kh, kl, vth, vtl, Yp);

    // Output projection (int8 IMMA)
    quant_kernel<<<SEQ, T>>>(Yp, ya1, ya2, sy, DIM);
    gemm_i8<<<dim3(DIM / 128, SEQ / 128), 256, I8_SMEM>>>(
        ya1, ya2, sy, woa1, woa2, swo, out, DIM);
}

// round 8
// speedup vs baseline: 2.1625x; 2.1625x over previous
#include <cuda_runtime.h>
#include <cuda_bf16.h>
#include <cuda_fp16.h>
#include <math.h>
#include <stdint.h>

#define SEQ    2048
#define DIM    4096
#define NH     32
#define NKV    8
#define HD     128
#define KVDIM  (NKV*HD)

// ---------------------------------------------------------------------------
// Scratch (device globals)
// ---------------------------------------------------------------------------
static __device__ float g_q[SEQ * DIM];
static __device__ float g_k[SEQ * KVDIM];
static __device__ float g_v[SEQ * KVDIM];

static __device__ __nv_bfloat16 g_xh[SEQ * DIM],    g_xl[SEQ * DIM];
static __device__ __nv_bfloat16 g_wqh[DIM * DIM],   g_wql[DIM * DIM];
static __device__ __nv_bfloat16 g_wkh[KVDIM * DIM], g_wkl[KVDIM * DIM];
static __device__ __nv_bfloat16 g_wvh[KVDIM * DIM], g_wvl[KVDIM * DIM];

static __device__ __half g_wo16[DIM * DIM];                 // Wo hi (fp16)
static __device__ __half g_yh16[SEQ * DIM], g_yl16[SEQ * DIM]; // Y hi/lo (fp16)

static __device__ __nv_bfloat16 g_qh[SEQ * DIM],    g_ql[SEQ * DIM];
static __device__ __nv_bfloat16 g_kh[SEQ * KVDIM],  g_kl[SEQ * KVDIM];
static __device__ __nv_bfloat16 g_vth[KVDIM * SEQ], g_vtl[KVDIM * SEQ];

// ---------------------------------------------------------------------------
// Helpers
// ---------------------------------------------------------------------------
__device__ __forceinline__ uint32_t smem_u32(const void* p) {
    uint32_t a;
    asm("{ .reg .u64 t; cvta.to.shared.u64 t, %1; cvt.u32.u64 %0, t; }"
        : "=r"(a) : "l"(p));
    return a;
}

__device__ __forceinline__ void ldsm_x4(uint32_t* d, uint32_t addr) {
    asm volatile("ldmatrix.sync.aligned.m8n8.x4.shared.b16 {%0,%1,%2,%3}, [%4];"
                 : "=r"(d[0]), "=r"(d[1]), "=r"(d[2]), "=r"(d[3]) : "r"(addr));
}

__device__ __forceinline__ void mma16816(float* c, const uint32_t* a,
                                         uint32_t b0, uint32_t b1) {
    asm volatile(
        "mma.sync.aligned.m16n8k16.row.col.f32.bf16.bf16.f32 "
        "{%0,%1,%2,%3}, {%4,%5,%6,%7}, {%8,%9}, {%0,%1,%2,%3};"
        : "+f"(c[0]), "+f"(c[1]), "+f"(c[2]), "+f"(c[3])
        : "r"(a[0]), "r"(a[1]), "r"(a[2]), "r"(a[3]), "r"(b0), "r"(b1));
}

__device__ __forceinline__ void mma16816h(float* c, const uint32_t* a,
                                          uint32_t b0, uint32_t b1) {
    asm volatile(
        "mma.sync.aligned.m16n8k16.row.col.f32.f16.f16.f32 "
        "{%0,%1,%2,%3}, {%4,%5,%6,%7}, {%8,%9}, {%0,%1,%2,%3};"
        : "+f"(c[0]), "+f"(c[1]), "+f"(c[2]), "+f"(c[3])
        : "r"(a[0]), "r"(a[1]), "r"(a[2]), "r"(a[3]), "r"(b0), "r"(b1));
}

#define CP_ASYNC16(dst, src) \
    asm volatile("cp.async.cg.shared.global [%0], [%1], 16;" :: "r"(dst), "l"(src))
#define CP_COMMIT() asm volatile("cp.async.commit_group;" ::: "memory")
#define CP_WAIT0()  asm volatile("cp.async.wait_group 0;"  ::: "memory")
#define CP_WAIT1()  asm volatile("cp.async.wait_group 1;"  ::: "memory")

__device__ __forceinline__ void split2(float a, __nv_bfloat16& h, __nv_bfloat16& l) {
    h = __float2bfloat16(a);
    l = __float2bfloat16(a - __bfloat162float(h));
}

// ---------------------------------------------------------------------------
// Pointwise kernels
// ---------------------------------------------------------------------------
__global__ void split_kernel(const float* __restrict__ in,
                             __nv_bfloat16* __restrict__ hi,
                             __nv_bfloat16* __restrict__ lo, int n8)
{
    int i = blockIdx.x * blockDim.x + threadIdx.x;
    if (i >= n8) return;
#pragma unroll
    for (int half = 0; half < 2; half++) {
        float4 v = ((const float4*)in)[2 * i + half];
        __nv_bfloat16 h0, h1, h2, h3, l0, l1, l2, l3;
        split2(v.x, h0, l0); split2(v.y, h1, l1);
        split2(v.z, h2, l2); split2(v.w, h3, l3);
        __nv_bfloat162* hp = (__nv_bfloat162*)hi;
        __nv_bfloat162* lp = (__nv_bfloat162*)lo;
        hp[4 * i + 2 * half]     = __nv_bfloat162(h0, h1);
        hp[4 * i + 2 * half + 1] = __nv_bfloat162(h2, h3);
        lp[4 * i + 2 * half]     = __nv_bfloat162(l0, l1);
        lp[4 * i + 2 * half + 1] = __nv_bfloat162(l2, l3);
    }
}

// fp32 -> fp16 (round-to-nearest), 8 per thread
__global__ void trunc16_kernel(const float* __restrict__ in,
                               __half* __restrict__ out, int n8)
{
    int i = blockIdx.x * blockDim.x + threadIdx.x;
    if (i >= n8) return;
#pragma unroll
    for (int half = 0; half < 2; half++) {
        float4 v = ((const float4*)in)[2 * i + half];
        __half2* op = (__half2*)out;
        op[4 * i + 2 * half]     = __halves2half2(__float2half_rn(v.x),
                                                  __float2half_rn(v.y));
        op[4 * i + 2 * half + 1] = __halves2half2(__float2half_rn(v.z),
                                                  __float2half_rn(v.w));
    }
}

__global__ void rope_split_kernel(const float* __restrict__ x,
                                  const float* __restrict__ fc,
                                  __nv_bfloat16* __restrict__ oh,
                                  __nv_bfloat16* __restrict__ ol,
                                  int nheads, float scale, int total)
{
    int idx = blockIdx.x * blockDim.x + threadIdx.x;
    if (idx >= total) return;
    const int i = idx & 63;
    const int h = (idx >> 6) % nheads;
    const int s = idx / (64 * nheads);
    const float c  = fc[(s * 64 + i) * 2 + 0];
    const float sn = fc[(s * 64 + i) * 2 + 1];
    const size_t off = ((size_t)s * nheads + h) * HD + 2 * i;
    float2 v = *(const float2*)(x + off);
    float a = (v.x * c - v.y * sn) * scale;
    float b = (v.y * c + v.x * sn) * scale;
    __nv_bfloat16 ah, al, bh, bl;
    split2(a, ah, al); split2(b, bh, bl);
    *(__nv_bfloat162*)(oh + off) = __nv_bfloat162(ah, bh);
    *(__nv_bfloat162*)(ol + off) = __nv_bfloat162(al, bl);
}

__global__ void split_vt_kernel(const float* __restrict__ v,
                                __nv_bfloat16* __restrict__ vh,
                                __nv_bfloat16* __restrict__ vl)
{
    int idx = blockIdx.x * blockDim.x + threadIdx.x;
    const int s = idx & (SEQ - 1);
    const int dl = idx >> 11;
    if (dl >= KVDIM) return;
    float val = v[(size_t)s * KVDIM + dl];
    __nv_bfloat16 h, l;
    split2(val, h, l);
    vh[idx] = h; vl[idx] = l;
}

// ---------------------------------------------------------------------------
// bf16 3-pass HMMA GEMM (R6, validated). CTA tile 128x256, 8 warps (2x4),
// warp tile 64x64, K-chunk 32, 3-stage cp.async.
// ---------------------------------------------------------------------------
#define GEMM_STAGE  49152
#define GEMM_SMEM   (3 * GEMM_STAGE + 1024)
#define GEMM_NC     (DIM / 32)

__device__ __forceinline__ void stage_load(
    uint32_t s_stage,
    const __nv_bfloat16* __restrict__ Ah, const __nv_bfloat16* __restrict__ Al,
    const __nv_bfloat16* __restrict__ Bh, const __nv_bfloat16* __restrict__ Bl,
    int row0, int col0, int k0, int tid)
{
    const int r  = tid >> 1;
    const int h  = tid & 1;
    const int sw = r & 7;
    {
        const __nv_bfloat16* src = (h ? Al : Ah) + (size_t)(row0 + r) * DIM + k0;
        const uint32_t rowp = s_stage + r * 128;
#pragma unroll
        for (int u = 0; u < 4; u++)
            CP_ASYNC16(rowp + (((h * 4 + u) ^ sw) * 16), src + u * 8);
    }
#pragma unroll
    for (int p = 0; p < 2; p++) {
        const int rb = r + p * 128;
        const int swb = rb & 7;
        const __nv_bfloat16* src = (h ? Bl : Bh) + (size_t)(col0 + rb) * DIM + k0;
        const uint32_t rowp = s_stage + 16384 + rb * 128;
#pragma unroll
        for (int u = 0; u < 4; u++)
            CP_ASYNC16(rowp + (((h * 4 + u) ^ swb) * 16), src + u * 8);
    }
}

__device__ __forceinline__ void gemm_body(
    const __nv_bfloat16* __restrict__ Ah, const __nv_bfloat16* __restrict__ Al,
    const __nv_bfloat16* __restrict__ Bh, const __nv_bfloat16* __restrict__ Bl,
    float* __restrict__ C, int Ntot, int row0, int col0, char* smraw)
{
    const uint32_t sbase = (smem_u32(smraw) + 1023u) & ~1023u;
    const int tid = threadIdx.x;
    const int lid = tid & 31;
    const int wid = tid >> 5;
    const int wm  = wid & 1;
    const int wn  = wid >> 1;

    float acc[4][8][4];
#pragma unroll
    for (int i = 0; i < 4; i++)
#pragma unroll
        for (int j = 0; j < 8; j++)
#pragma unroll
            for (int q = 0; q < 4; q++) acc[i][j][q] = 0.f;

    stage_load(sbase,              Ah, Al, Bh, Bl, row0, col0, 0,  tid);
    CP_COMMIT();
    stage_load(sbase + GEMM_STAGE, Ah, Al, Bh, Bl, row0, col0, 32, tid);
    CP_COMMIT();

    int cur = 0, nxt = 2;
    for (int c = 0; c < GEMM_NC; c++) {
        CP_WAIT1();
        __syncthreads();
        if (c + 2 < GEMM_NC) {
            stage_load(sbase + nxt * GEMM_STAGE,
                       Ah, Al, Bh, Bl, row0, col0, (c + 2) * 32, tid);
            CP_COMMIT();
        }
        const uint32_t aBase = sbase + cur * GEMM_STAGE;
        const uint32_t bBase = aBase + 16384;
        cur = (cur == 2) ? 0 : cur + 1;
        nxt = (nxt == 2) ? 0 : nxt + 1;

#pragma unroll
        for (int ks = 0; ks < 2; ks++) {
            uint32_t af[4][4], bhf[4][4], blf[4][4];
#pragma unroll
            for (int mt = 0; mt < 4; mt++) {
                const int r = wm * 64 + mt * 16 + (lid & 15);
                const int lu = ks * 2 + (lid >> 4);
                ldsm_x4(af[mt], aBase + r * 128 + ((lu ^ (r & 7)) * 16));
            }
#pragma unroll
            for (int np = 0; np < 4; np++) {
                const int r  = wn * 64 + np * 16 + ((lid >> 4) & 1) * 8 + (lid & 7);
                const int lu = ks * 2 + ((lid >> 3) & 1);
                ldsm_x4(bhf[np], bBase + r * 128 + ((lu ^ (r & 7)) * 16));
                ldsm_x4(blf[np], bBase + r * 128 + (((lu + 4) ^ (r & 7)) * 16));
            }
#pragma unroll
            for (int mt = 0; mt < 4; mt++)
#pragma unroll
                for (int nt = 0; nt < 8; nt++) {
                    mma16816(acc[mt][nt], af[mt],
                             bhf[nt >> 1][(nt & 1) * 2], bhf[nt >> 1][(nt & 1) * 2 + 1]);
                    mma16816(acc[mt][nt], af[mt],
                             blf[nt >> 1][(nt & 1) * 2], blf[nt >> 1][(nt & 1) * 2 + 1]);
                }
#pragma unroll
            for (int mt = 0; mt < 4; mt++) {
                const int r = wm * 64 + mt * 16 + (lid & 15);
                const int lu = 4 + ks * 2 + (lid >> 4);
                ldsm_x4(af[mt], aBase + r * 128 + ((lu ^ (r & 7)) * 16));
            }
#pragma unroll
            for (int mt = 0; mt < 4; mt++)
#pragma unroll
                for (int nt = 0; nt < 8; nt++)
                    mma16816(acc[mt][nt], af[mt],
                             bhf[nt >> 1][(nt & 1) * 2], bhf[nt >> 1][(nt & 1) * 2 + 1]);
        }
    }

#pragma unroll
    for (int mt = 0; mt < 4; mt++) {
        const int r = row0 + wm * 64 + mt * 16 + (lid >> 2);
#pragma unroll
        for (int nt = 0; nt < 8; nt++) {
            const int cc = col0 + wn * 64 + nt * 8 + (lid & 3) * 2;
            *(float2*)&C[(size_t)r * Ntot + cc] =
                make_float2(acc[mt][nt][0], acc[mt][nt][1]);
            *(float2*)&C[(size_t)(r + 8) * Ntot + cc] =
                make_float2(acc[mt][nt][2], acc[mt][nt][3]);
        }
    }
}

// Fused QKV: blockIdx.x 0..23 (0-15 Q, 16-19 K, 20-23 V)
__global__ void __launch_bounds__(256, 1)
gemm_qkv_kernel(const __nv_bfloat16* __restrict__ xh,
                const __nv_bfloat16* __restrict__ xl,
                const __nv_bfloat16* __restrict__ wqh, const __nv_bfloat16* __restrict__ wql,
                const __nv_bfloat16* __restrict__ wkh, const __nv_bfloat16* __restrict__ wkl,
                const __nv_bfloat16* __restrict__ wvh, const __nv_bfloat16* __restrict__ wvl,
                float* __restrict__ Q, float* __restrict__ K, float* __restrict__ V)
{
    extern __shared__ char smraw[];
    const int xb = blockIdx.x;
    const int row0 = blockIdx.y * 128;
    const __nv_bfloat16 *Bh, *Bl;
    float* C; int Ntot, col0;
    if (xb < 16)      { Bh = wqh; Bl = wql; C = Q; Ntot = DIM;   col0 = xb * 256; }
    else if (xb < 20) { Bh = wkh; Bl = wkl; C = K; Ntot = KVDIM; col0 = (xb - 16) * 256; }
    else              { Bh = wvh; Bl = wvl; C = V; Ntot = KVDIM; col0 = (xb - 20) * 256; }
    gemm_body(xh, xl, Bh, Bl, C, Ntot, row0, col0, smraw);
}

// ---------------------------------------------------------------------------
// fp16 2-pass GEMM for the output projection:
// C = Yh @ Wh^T + Yl @ Wh^T   (drops Wo-lo; error ~2^-11 on Wo only).
// CTA tile 128x256, K-chunk 64. Stage 64KB: A sub0 16K | A sub1 16K | B 32K.
// A row (128B): [hi 32 f16 | lo 32 f16]; B row (128B): 64 f16 of one k64.
// ---------------------------------------------------------------------------
#define F2_STAGE 65536
#define F2_SMEM  (3 * F2_STAGE + 1024)
#define F2_NC    (DIM / 64)

__device__ __forceinline__ void f2_stage_load(
    uint32_t st, const __half* __restrict__ Yh, const __half* __restrict__ Yl,
    const __half* __restrict__ Wh, int row0, int col0, int k0, int tid)
{
    const int r  = tid >> 1;
    const int h  = tid & 1;
    const int sw = r & 7;
    // A: two k32 sub-chunks
#pragma unroll
    for (int s = 0; s < 2; s++) {
        const __half* src = (h ? Yl : Yh) + (size_t)(row0 + r) * DIM + k0 + s * 32;
        const uint32_t rowp = st + s * 16384 + r * 128;
#pragma unroll
        for (int u = 0; u < 4; u++)
            CP_ASYNC16(rowp + (((h * 4 + u) ^ sw) * 16), src + u * 8);
    }
    // B: 256 rows x 128B (k64), two passes, 8 units each (each thread does half)
#pragma unroll
    for (int p = 0; p < 2; p++) {
        const int rb = r + p * 128;
        const int swb = rb & 7;
        const __half* src = Wh + (size_t)(col0 + rb) * DIM + k0 + h * 32;
        const uint32_t rowp = st + 32768 + rb * 128;
#pragma unroll
        for (int u = 0; u < 4; u++)
            CP_ASYNC16(rowp + (((h * 4 + u) ^ swb) * 16), src + u * 8);
    }
}

__global__ void __launch_bounds__(256, 1)
gemm_f16_2p(const __half* __restrict__ Yh, const __half* __restrict__ Yl,
            const __half* __restrict__ Wh, float* __restrict__ C, int Ntot)
{
    extern __shared__ char smraw[];
    const uint32_t sbase = (smem_u32(smraw) + 1023u) & ~1023u;
    const int tid = threadIdx.x;
    const int lid = tid & 31;
    const int wid = tid >> 5;
    const int wm  = wid & 1;
    const int wn  = wid >> 1;
    const int row0 = blockIdx.y * 128;
    const int col0 = blockIdx.x * 256;

    float acc[4][8][4];
#pragma unroll
    for (int i = 0; i < 4; i++)
#pragma unroll
        for (int j = 0; j < 8; j++)
#pragma unroll
            for (int q = 0; q < 4; q++) acc[i][j][q] = 0.f;

    f2_stage_load(sbase,            Yh, Yl, Wh, row0, col0, 0,  tid);
    CP_COMMIT();
    f2_stage_load(sbase + F2_STAGE, Yh, Yl, Wh, row0, col0, 64, tid);
    CP_COMMIT();

    int cur = 0, nxt = 2;
    for (int c = 0; c < F2_NC; c++) {
        CP_WAIT1();
        __syncthreads();
        if (c + 2 < F2_NC) {
            f2_stage_load(sbase + nxt * F2_STAGE,
                          Yh, Yl, Wh, row0, col0, (c + 2) * 64, tid);
            CP_COMMIT();
        }
        const uint32_t aBase = sbase + cur * F2_STAGE;
        const uint32_t bBase = aBase + 32768;
        cur = (cur == 2) ? 0 : cur + 1;
        nxt = (nxt == 2) ? 0 : nxt + 1;

#pragma unroll
        for (int ks = 0; ks < 4; ks++) {     // 4 k16 steps per k64 chunk
            const int sub = ks >> 1;
            uint32_t ahf[4][4], alf[4][4], bf[4][4];
#pragma unroll
            for (int mt = 0; mt < 4; mt++) {
                const int r = wm * 64 + mt * 16 + (lid & 15);
                const int luh = (ks & 1) * 2 + (lid >> 4);
                const uint32_t rowp = aBase + sub * 16384 + r * 128;
                ldsm_x4(ahf[mt], rowp + ((luh ^ (r & 7)) * 16));
                ldsm_x4(alf[mt], rowp + (((luh + 4) ^ (r & 7)) * 16));
            }
#pragma unroll
            for (int np = 0; np < 4; np++) {
                const int r  = wn * 64 + np * 16 + ((lid >> 4) & 1) * 8 + (lid & 7);
                const int lu = ks * 2 + ((lid >> 3) & 1);
                ldsm_x4(bf[np], bBase + r * 128 + ((lu ^ (r & 7)) * 16));
            }
#pragma unroll
            for (int mt = 0; mt < 4; mt++)
#pragma unroll
                for (int nt = 0; nt < 8; nt++) {
                    mma16816h(acc[mt][nt], ahf[mt],
                              bf[nt >> 1][(nt & 1) * 2], bf[nt >> 1][(nt & 1) * 2 + 1]);
                    mma16816h(acc[mt][nt], alf[mt],
                              bf[nt >> 1][(nt & 1) * 2], bf[nt >> 1][(nt & 1) * 2 + 1]);
                }
        }
    }

#pragma unroll
    for (int mt = 0; mt < 4; mt++) {
        const int r = row0 + wm * 64 + mt * 16 + (lid >> 2);
#pragma unroll
        for (int nt = 0; nt < 8; nt++) {
            const int cc = col0 + wn * 64 + nt * 8 + (lid & 3) * 2;
            *(float2*)&C[(size_t)r * Ntot + cc] =
                make_float2(acc[mt][nt][0], acc[mt][nt][1]);
            *(float2*)&C[(size_t)(r + 8) * Ntot + cc] =
                make_float2(acc[mt][nt][2], acc[mt][nt][3]);
        }
    }
}

// ---------------------------------------------------------------------------
// HMMA flash attention (validated R6). Br=128, Bc=64, causal, GQA rep 4.
// Epilogue now writes Y as fp16 hi/lo (for the 2-pass output projection).
// ---------------------------------------------------------------------------
#define AT_QH 0
#define AT_QL 32768
#define AT_ST(b) (65536 + (b) * 65536)
#define AT_KH 0
#define AT_KL 16384
#define AT_VH 32768
#define AT_VL 49152
#define AT_SMEM (65536 + 2 * 65536)

__device__ __forceinline__ void attn_load_kv(
    uint32_t stage, const __nv_bfloat16* __restrict__ Kh,
    const __nv_bfloat16* __restrict__ Kl,
    const __nv_bfloat16* __restrict__ Vth, const __nv_bfloat16* __restrict__ Vtl,
    int j, int kvh, int tid)
{
    for (int idx = tid; idx < 1024; idx += 256) {
        const int r = idx >> 4, u = idx & 15;
        const int phys = ((u ^ (r & 7)) * 16);
        const size_t gk = ((size_t)(j * 64 + r) * NKV + kvh) * HD + u * 8;
        CP_ASYNC16(stage + AT_KH + r * 256 + phys, Kh + gk);
        CP_ASYNC16(stage + AT_KL + r * 256 + phys, Kl + gk);
    }
    for (int idx = tid; idx < 1024; idx += 256) {
        const int r = idx >> 3, u = idx & 7;
        const int phys = ((u ^ (r & 7)) * 16);
        const size_t gv = ((size_t)(kvh * 128 + r)) * SEQ + j * 64 + u * 8;
        CP_ASYNC16(stage + AT_VH + r * 128 + phys, Vth + gv);
        CP_ASYNC16(stage + AT_VL + r * 128 + phys, Vtl + gv);
    }
}

__global__ void __launch_bounds__(256, 1)
attn_hmma_kernel(const __nv_bfloat16* __restrict__ Qh,
                 const __nv_bfloat16* __restrict__ Ql,
                 const __nv_bfloat16* __restrict__ Kh,
                 const __nv_bfloat16* __restrict__ Kl,
                 const __nv_bfloat16* __restrict__ Vth,
                 const __nv_bfloat16* __restrict__ Vtl,
                 __half* __restrict__ Yh, __half* __restrict__ Yl)
{
    extern __shared__ char smraw[];
    const uint32_t sb = smem_u32(smraw);

    const int qt  = blockIdx.x;
    const int h   = blockIdx.y;
    const int kvh = h >> 2;
    const int tid = threadIdx.x;
    const int lid = tid & 31;
    const int wid = tid >> 5;
    const int qrow0 = qt * 128;

    for (int idx = tid; idx < 2048; idx += 256) {
        const int r = idx >> 4, u = idx & 15;
        const int phys = ((u ^ (r & 7)) * 16);
        const size_t g = ((size_t)(qrow0 + r) * NH + h) * HD + u * 8;
        CP_ASYNC16(sb + AT_QH + r * 256 + phys, Qh + g);
        CP_ASYNC16(sb + AT_QL + r * 256 + phys, Ql + g);
    }
    attn_load_kv(sb + AT_ST(0), Kh, Kl, Vth, Vtl, 0, kvh, tid);
    CP_COMMIT();

    float o[16][4];
#pragma unroll
    for (int dt = 0; dt < 16; dt++)
#pragma unroll
        for (int q = 0; q < 4; q++) o[dt][q] = 0.f;
    float mA = -1e30f, mB = -1e30f, lA = 0.f, lB = 0.f;

    const int g  = lid >> 2;
    const int cA = (lid & 3) * 2;
    const int jEnd = 2 * qt + 1;

    for (int j = 0; j <= jEnd; j++) {
        CP_WAIT0();
        __syncthreads();
        if (j < jEnd) {
            attn_load_kv(sb + AT_ST((j + 1) & 1), Kh, Kl, Vth, Vtl, j + 1, kvh, tid);
            CP_COMMIT();
        }
        const uint32_t kb = sb + AT_ST(j & 1);

        float s[8][4];
#pragma unroll
        for (int nt = 0; nt < 8; nt++)
#pragma unroll
            for (int q = 0; q < 4; q++) s[nt][q] = 0.f;

#pragma unroll
        for (int kc = 0; kc < 8; kc++) {
            uint32_t qhf[4], qlf[4];
            const int rA = wid * 16 + (lid & 15);
            const int uA = kc * 2 + (lid >> 4);
            ldsm_x4(qhf, sb + AT_QH + rA * 256 + ((uA ^ (rA & 7)) * 16));
            ldsm_x4(qlf, sb + AT_QL + rA * 256 + ((uA ^ (rA & 7)) * 16));
#pragma unroll
            for (int np = 0; np < 4; np++) {
                uint32_t khf[4], klf[4];
                const int rB = np * 16 + ((lid >> 4) & 1) * 8 + (lid & 7);
                const int uB = kc * 2 + ((lid >> 3) & 1);
                ldsm_x4(khf, kb + AT_KH + rB * 256 + ((uB ^ (rB & 7)) * 16));
                ldsm_x4(klf, kb + AT_KL + rB * 256 + ((uB ^ (rB & 7)) * 16));
#pragma unroll
                for (int hf = 0; hf < 2; hf++) {
                    const int nt = np * 2 + hf;
                    mma16816(s[nt], qhf, khf[hf * 2], khf[hf * 2 + 1]);
                    mma16816(s[nt], qhf, klf[hf * 2], klf[hf * 2 + 1]);
                    mma16816(s[nt], qlf, khf[hf * 2], khf[hf * 2 + 1]);
                }
            }
        }

        if (j >= 2 * qt) {
            const int rowA = qrow0 + wid * 16 + g;
            const int colBase = j * 64;
#pragma unroll
            for (int nt = 0; nt < 8; nt++) {
                const int col = colBase + nt * 8 + cA;
                if (col     > rowA)     s[nt][0] = -1e30f;
                if (col + 1 > rowA)     s[nt][1] = -1e30f;
                if (col     > rowA + 8) s[nt][2] = -1e30f;
                if (col + 1 > rowA + 8) s[nt][3] = -1e30f;
            }
        }

        float mxA = -1e30f, mxB = -1e30f;
#pragma unroll
        for (int nt = 0; nt < 8; nt++) {
            mxA = fmaxf(mxA, fmaxf(s[nt][0], s[nt][1]));
            mxB = fmaxf(mxB, fmaxf(s[nt][2], s[nt][3]));
        }
        mxA = fmaxf(mxA, __shfl_xor_sync(0xffffffffu, mxA, 1));
        mxA = fmaxf(mxA, __shfl_xor_sync(0xffffffffu, mxA, 2));
        mxB = fmaxf(mxB, __shfl_xor_sync(0xffffffffu, mxB, 1));
        mxB = fmaxf(mxB, __shfl_xor_sync(0xffffffffu, mxB, 2));
        const float mnA = fmaxf(mA, mxA), mnB = fmaxf(mB, mxB);
        const float alA = __expf(mA - mnA), alB = __expf(mB - mnB);

        uint32_t ph[8][2], pl[8][2];
        float rsA = 0.f, rsB = 0.f;
#pragma unroll
        for (int nt = 0; nt < 8; nt++) {
            float p0 = __expf(s[nt][0] - mnA);
            float p1 = __expf(s[nt][1] - mnA);
            float p2 = __expf(s[nt][2] - mnB);
            float p3 = __expf(s[nt][3] - mnB);
            rsA += p0 + p1;  rsB += p2 + p3;
            __nv_bfloat16 h0, h1, h2, h3, e0, e1, e2, e3;
            split2(p0, h0, e0); split2(p1, h1, e1);
            split2(p2, h2, e2); split2(p3, h3, e3);
            __nv_bfloat162 a0(h0, h1), a1(h2, h3), b0(e0, e1), b1(e2, e3);
            ph[nt][0] = *reinterpret_cast<uint32_t*>(&a0);
            ph[nt][1] = *reinterpret_cast<uint32_t*>(&a1);
            pl[nt][0] = *reinterpret_cast<uint32_t*>(&b0);
            pl[nt][1] = *reinterpret_cast<uint32_t*>(&b1);
        }
        rsA += __shfl_xor_sync(0xffffffffu, rsA, 1);
        rsA += __shfl_xor_sync(0xffffffffu, rsA, 2);
        rsB += __shfl_xor_sync(0xffffffffu, rsB, 1);
        rsB += __shfl_xor_sync(0xffffffffu, rsB, 2);
        lA = lA * alA + rsA;  mA = mnA;
        lB = lB * alB + rsB;  mB = mnB;

#pragma unroll
        for (int dt = 0; dt < 16; dt++) {
            o[dt][0] *= alA; o[dt][1] *= alA;
            o[dt][2] *= alB; o[dt][3] *= alB;
        }

#pragma unroll
        for (int kc = 0; kc < 4; kc++) {
            uint32_t aH[4] = { ph[2 * kc][0], ph[2 * kc][1],
                               ph[2 * kc + 1][0], ph[2 * kc + 1][1] };
            uint32_t aL[4] = { pl[2 * kc][0], pl[2 * kc][1],
                               pl[2 * kc + 1][0], pl[2 * kc + 1][1] };
#pragma unroll
            for (int dp = 0; dp < 8; dp++) {
                uint32_t vhf[4], vlf[4];
                const int rB = dp * 16 + ((lid >> 4) & 1) * 8 + (lid & 7);
                const int uB = kc * 2 + ((lid >> 3) & 1);
                ldsm_x4(vhf, kb + AT_VH + rB * 128 + ((uB ^ (rB & 7)) * 16));
                ldsm_x4(vlf, kb + AT_VL + rB * 128 + ((uB ^ (rB & 7)) * 16));
#pragma unroll
                for (int hf = 0; hf < 2; hf++) {
                    const int dt = dp * 2 + hf;
                    mma16816(o[dt], aH, vhf[hf * 2], vhf[hf * 2 + 1]);
                    mma16816(o[dt], aL, vhf[hf * 2], vhf[hf * 2 + 1]);
                    mma16816(o[dt], aH, vlf[hf * 2], vlf[hf * 2 + 1]);
                }
            }
        }
    }

    // Epilogue: write Y as fp16 hi/lo
    const float invA = 1.f / lA, invB = 1.f / lB;
    const int rowA = qrow0 + wid * 16 + g;
#pragma unroll
    for (int dt = 0; dt < 16; dt++) {
        const int d = h * HD + dt * 8 + cA;
        {
            float v0 = o[dt][0] * invA, v1 = o[dt][1] * invA;
            __half h0 = __float2half_rn(v0), h1 = __float2half_rn(v1);
            __half l0 = __float2half_rn(v0 - __half2float(h0));
            __half l1 = __float2half_rn(v1 - __half2float(h1));
            *(__half2*)&Yh[(size_t)rowA * DIM + d] = __halves2half2(h0, h1);
            *(__half2*)&Yl[(size_t)rowA * DIM + d] = __halves2half2(l0, l1);
        }
        {
            float v0 = o[dt][2] * invB, v1 = o[dt][3] * invB;
            __half h0 = __float2half_rn(v0), h1 = __float2half_rn(v1);
            __half l0 = __float2half_rn(v0 - __half2float(h0));
            __half l1 = __float2half_rn(v1 - __half2float(h1));
            *(__half2*)&Yh[(size_t)(rowA + 8) * DIM + d] = __halves2half2(h0, h1);
            *(__half2*)&Yl[(size_t)(rowA + 8) * DIM + d] = __halves2half2(l0, l1);
        }
    }
}

// ---------------------------------------------------------------------------
// Launch
// ---------------------------------------------------------------------------
extern "C" void kernel_launch(void* const* d_in, const int* in_sizes, int n_in,
                              void* d_out, int out_size)
{
    const float* x  = (const float*)d_in[0];
    const float* fc = (const float*)d_in[1];
    const float* wq = (const float*)d_in[3];
    const float* wk = (const float*)d_in[4];
    const float* wv = (const float*)d_in[5];
    const float* wo = (const float*)d_in[6];
    float* out = (float*)d_out;

    float *Q, *Kp, *Vp;
    cudaGetSymbolAddress((void**)&Q,  g_q);
    cudaGetSymbolAddress((void**)&Kp, g_k);
    cudaGetSymbolAddress((void**)&Vp, g_v);

    __nv_bfloat16 *xh, *xl, *wqh, *wql, *wkh, *wkl, *wvh, *wvl;
    __nv_bfloat16 *qh, *ql, *kh, *kl, *vth, *vtl;
    __half *wo16, *yh16, *yl16;
    cudaGetSymbolAddress((void**)&xh,  g_xh);  cudaGetSymbolAddress((void**)&xl,  g_xl);
    cudaGetSymbolAddress((void**)&wqh, g_wqh); cudaGetSymbolAddress((void**)&wql, g_wql);
    cudaGetSymbolAddress((void**)&wkh, g_wkh); cudaGetSymbolAddress((void**)&wkl, g_wkl);
    cudaGetSymbolAddress((void**)&wvh, g_wvh); cudaGetSymbolAddress((void**)&wvl, g_wvl);
    cudaGetSymbolAddress((void**)&qh,  g_qh);  cudaGetSymbolAddress((void**)&ql,  g_ql);
    cudaGetSymbolAddress((void**)&kh,  g_kh);  cudaGetSymbolAddress((void**)&kl,  g_kl);
    cudaGetSymbolAddress((void**)&vth, g_vth); cudaGetSymbolAddress((void**)&vtl, g_vtl);
    cudaGetSymbolAddress((void**)&wo16, g_wo16);
    cudaGetSymbolAddress((void**)&yh16, g_yh16);
    cudaGetSymbolAddress((void**)&yl16, g_yl16);

    cudaFuncSetAttribute(gemm_qkv_kernel,
                         cudaFuncAttributeMaxDynamicSharedMemorySize, GEMM_SMEM);
    cudaFuncSetAttribute(gemm_f16_2p,
                         cudaFuncAttributeMaxDynamicSharedMemorySize, F2_SMEM);
    cudaFuncSetAttribute(attn_hmma_kernel,
                         cudaFuncAttributeMaxDynamicSharedMemorySize, AT_SMEM);

    const int T = 256;
    split_kernel<<<(SEQ * DIM / 8 + T - 1) / T, T>>>(x,  xh,  xl,  SEQ * DIM / 8);
    split_kernel<<<(DIM * DIM / 8 + T - 1) / T, T>>>(wq, wqh, wql, DIM * DIM / 8);
    split_kernel<<<(KVDIM * DIM / 8 + T - 1) / T, T>>>(wk, wkh, wkl, KVDIM * DIM / 8);
    split_kernel<<<(KVDIM * DIM / 8 + T - 1) / T, T>>>(wv, wvh, wvl, KVDIM * DIM / 8);
    trunc16_kernel<<<(DIM * DIM / 8 + T - 1) / T, T>>>(wo, wo16, DIM * DIM / 8);

    // Fused QKV projection (bf16 3-pass)
    gemm_qkv_kernel<<<dim3(24, SEQ / 128), 256, GEMM_SMEM>>>(
        xh, xl, wqh, wql, wkh, wkl, wvh, wvl, Q, Kp, Vp);

    // RoPE + split; V transpose + split
    const float scale = 0.08838834764831845f;
    rope_split_kernel<<<(SEQ * NH  * 64 + T - 1) / T, T>>>(
        Q,  fc, qh, ql, NH,  scale, SEQ * NH  * 64);
    rope_split_kernel<<<(SEQ * NKV * 64 + T - 1) / T, T>>>(
        Kp, fc, kh, kl, NKV, 1.0f,  SEQ * NKV * 64);
    split_vt_kernel<<<(KVDIM * SEQ + T - 1) / T, T>>>(Vp, vth, vtl);

    // Attention (split-bf16 HMMA, Br=128) -> Y fp16 hi/lo
    attn_hmma_kernel<<<dim3(SEQ / 128, NH), 256, AT_SMEM>>>(
        qh, ql, kh, kl, vth, vtl, yh16, yl16);

    // Output projection (fp16 2-pass)
    gemm_f16_2p<<<dim3(DIM / 256, SEQ / 128), 256, F2_SMEM>>>(
        yh16, yl16, wo16, out, DIM);
}

// round 9
// speedup vs baseline: 2.3433x; 1.0836x over previous
#include <cuda_runtime.h>
#include <cuda_bf16.h>
#include <cuda_fp16.h>
#include <math.h>
#include <stdint.h>

#define SEQ    2048
#define DIM    4096
#define NH     32
#define NKV    8
#define HD     128
#define KVDIM  (NKV*HD)

// ---------------------------------------------------------------------------
// Scratch (device globals)
// ---------------------------------------------------------------------------
static __device__ float g_q[SEQ * DIM];
static __device__ float g_k[SEQ * KVDIM];
static __device__ float g_v[SEQ * KVDIM];

static __device__ __nv_bfloat16 g_xh[SEQ * DIM],    g_xl[SEQ * DIM];
static __device__ __nv_bfloat16 g_wqh[DIM * DIM],   g_wql[DIM * DIM];
static __device__ __nv_bfloat16 g_wkh[KVDIM * DIM], g_wkl[KVDIM * DIM];
static __device__ __nv_bfloat16 g_wvh[KVDIM * DIM], g_wvl[KVDIM * DIM];

static __device__ __half g_wo16[DIM * DIM];
static __device__ __half g_yh16[SEQ * DIM], g_yl16[SEQ * DIM];

// fp16 attention operands
static __device__ __half g_q16[SEQ * DIM];
static __device__ __half g_k16[SEQ * KVDIM];
static __device__ __half g_vt16[KVDIM * SEQ];   // [kvh*128+d][s]

// ---------------------------------------------------------------------------
// Helpers
// ---------------------------------------------------------------------------
__device__ __forceinline__ uint32_t smem_u32(const void* p) {
    uint32_t a;
    asm("{ .reg .u64 t; cvta.to.shared.u64 t, %1; cvt.u32.u64 %0, t; }"
        : "=r"(a) : "l"(p));
    return a;
}

__device__ __forceinline__ void ldsm_x4(uint32_t* d, uint32_t addr) {
    asm volatile("ldmatrix.sync.aligned.m8n8.x4.shared.b16 {%0,%1,%2,%3}, [%4];"
                 : "=r"(d[0]), "=r"(d[1]), "=r"(d[2]), "=r"(d[3]) : "r"(addr));
}

__device__ __forceinline__ void mma16816(float* c, const uint32_t* a,
                                         uint32_t b0, uint32_t b1) {
    asm volatile(
        "mma.sync.aligned.m16n8k16.row.col.f32.bf16.bf16.f32 "
        "{%0,%1,%2,%3}, {%4,%5,%6,%7}, {%8,%9}, {%0,%1,%2,%3};"
        : "+f"(c[0]), "+f"(c[1]), "+f"(c[2]), "+f"(c[3])
        : "r"(a[0]), "r"(a[1]), "r"(a[2]), "r"(a[3]), "r"(b0), "r"(b1));
}

__device__ __forceinline__ void mma16816h(float* c, const uint32_t* a,
                                          uint32_t b0, uint32_t b1) {
    asm volatile(
        "mma.sync.aligned.m16n8k16.row.col.f32.f16.f16.f32 "
        "{%0,%1,%2,%3}, {%4,%5,%6,%7}, {%8,%9}, {%0,%1,%2,%3};"
        : "+f"(c[0]), "+f"(c[1]), "+f"(c[2]), "+f"(c[3])
        : "r"(a[0]), "r"(a[1]), "r"(a[2]), "r"(a[3]), "r"(b0), "r"(b1));
}

#define CP_ASYNC16(dst, src) \
    asm volatile("cp.async.cg.shared.global [%0], [%1], 16;" :: "r"(dst), "l"(src))
#define CP_COMMIT() asm volatile("cp.async.commit_group;" ::: "memory")
#define CP_WAIT0()  asm volatile("cp.async.wait_group 0;"  ::: "memory")
#define CP_WAIT1()  asm volatile("cp.async.wait_group 1;"  ::: "memory")

__device__ __forceinline__ void split2(float a, __nv_bfloat16& h, __nv_bfloat16& l) {
    h = __float2bfloat16(a);
    l = __float2bfloat16(a - __bfloat162float(h));
}

// ---------------------------------------------------------------------------
// Pointwise kernels
// ---------------------------------------------------------------------------
__global__ void split_kernel(const float* __restrict__ in,
                             __nv_bfloat16* __restrict__ hi,
                             __nv_bfloat16* __restrict__ lo, int n8)
{
    int i = blockIdx.x * blockDim.x + threadIdx.x;
    if (i >= n8) return;
#pragma unroll
    for (int half = 0; half < 2; half++) {
        float4 v = ((const float4*)in)[2 * i + half];
        __nv_bfloat16 h0, h1, h2, h3, l0, l1, l2, l3;
        split2(v.x, h0, l0); split2(v.y, h1, l1);
        split2(v.z, h2, l2); split2(v.w, h3, l3);
        __nv_bfloat162* hp = (__nv_bfloat162*)hi;
        __nv_bfloat162* lp = (__nv_bfloat162*)lo;
        hp[4 * i + 2 * half]     = __nv_bfloat162(h0, h1);
        hp[4 * i + 2 * half + 1] = __nv_bfloat162(h2, h3);
        lp[4 * i + 2 * half]     = __nv_bfloat162(l0, l1);
        lp[4 * i + 2 * half + 1] = __nv_bfloat162(l2, l3);
    }
}

__global__ void trunc16_kernel(const float* __restrict__ in,
                               __half* __restrict__ out, int n8)
{
    int i = blockIdx.x * blockDim.x + threadIdx.x;
    if (i >= n8) return;
#pragma unroll
    for (int half = 0; half < 2; half++) {
        float4 v = ((const float4*)in)[2 * i + half];
        __half2* op = (__half2*)out;
        op[4 * i + 2 * half]     = __floats2half2_rn(v.x, v.y);
        op[4 * i + 2 * half + 1] = __floats2half2_rn(v.z, v.w);
    }
}

// RoPE + scale -> single fp16
__global__ void rope_f16_kernel(const float* __restrict__ x,
                                const float* __restrict__ fc,
                                __half* __restrict__ o,
                                int nheads, float scale, int total)
{
    int idx = blockIdx.x * blockDim.x + threadIdx.x;
    if (idx >= total) return;
    const int i = idx & 63;
    const int h = (idx >> 6) % nheads;
    const int s = idx / (64 * nheads);
    const float c  = fc[(s * 64 + i) * 2 + 0];
    const float sn = fc[(s * 64 + i) * 2 + 1];
    const size_t off = ((size_t)s * nheads + h) * HD + 2 * i;
    float2 v = *(const float2*)(x + off);
    float a = (v.x * c - v.y * sn) * scale;
    float b = (v.y * c + v.x * sn) * scale;
    *(__half2*)(o + off) = __floats2half2_rn(a, b);
}

// V transpose -> fp16: [s][dl] -> [dl][s]
__global__ void vt_f16_kernel(const float* __restrict__ v,
                              __half* __restrict__ vt)
{
    int idx = blockIdx.x * blockDim.x + threadIdx.x;
    const int s = idx & (SEQ - 1);
    const int dl = idx >> 11;
    if (dl >= KVDIM) return;
    vt[idx] = __float2half_rn(v[(size_t)s * KVDIM + dl]);
}

// ---------------------------------------------------------------------------
// bf16 3-pass HMMA GEMM (validated). CTA tile 128x256, 8 warps.
// ---------------------------------------------------------------------------
#define GEMM_STAGE  49152
#define GEMM_SMEM   (3 * GEMM_STAGE + 1024)
#define GEMM_NC     (DIM / 32)

__device__ __forceinline__ void stage_load(
    uint32_t s_stage,
    const __nv_bfloat16* __restrict__ Ah, const __nv_bfloat16* __restrict__ Al,
    const __nv_bfloat16* __restrict__ Bh, const __nv_bfloat16* __restrict__ Bl,
    int row0, int col0, int k0, int tid)
{
    const int r  = tid >> 1;
    const int h  = tid & 1;
    const int sw = r & 7;
    {
        const __nv_bfloat16* src = (h ? Al : Ah) + (size_t)(row0 + r) * DIM + k0;
        const uint32_t rowp = s_stage + r * 128;
#pragma unroll
        for (int u = 0; u < 4; u++)
            CP_ASYNC16(rowp + (((h * 4 + u) ^ sw) * 16), src + u * 8);
    }
#pragma unroll
    for (int p = 0; p < 2; p++) {
        const int rb = r + p * 128;
        const int swb = rb & 7;
        const __nv_bfloat16* src = (h ? Bl : Bh) + (size_t)(col0 + rb) * DIM + k0;
        const uint32_t rowp = s_stage + 16384 + rb * 128;
#pragma unroll
        for (int u = 0; u < 4; u++)
            CP_ASYNC16(rowp + (((h * 4 + u) ^ swb) * 16), src + u * 8);
    }
}

__device__ __forceinline__ void gemm_body(
    const __nv_bfloat16* __restrict__ Ah, const __nv_bfloat16* __restrict__ Al,
    const __nv_bfloat16* __restrict__ Bh, const __nv_bfloat16* __restrict__ Bl,
    float* __restrict__ C, int Ntot, int row0, int col0, char* smraw)
{
    const uint32_t sbase = (smem_u32(smraw) + 1023u) & ~1023u;
    const int tid = threadIdx.x;
    const int lid = tid & 31;
    const int wid = tid >> 5;
    const int wm  = wid & 1;
    const int wn  = wid >> 1;

    float acc[4][8][4];
#pragma unroll
    for (int i = 0; i < 4; i++)
#pragma unroll
        for (int j = 0; j < 8; j++)
#pragma unroll
            for (int q = 0; q < 4; q++) acc[i][j][q] = 0.f;

    stage_load(sbase,              Ah, Al, Bh, Bl, row0, col0, 0,  tid);
    CP_COMMIT();
    stage_load(sbase + GEMM_STAGE, Ah, Al, Bh, Bl, row0, col0, 32, tid);
    CP_COMMIT();

    int cur = 0, nxt = 2;
    for (int c = 0; c < GEMM_NC; c++) {
        CP_WAIT1();
        __syncthreads();
        if (c + 2 < GEMM_NC) {
            stage_load(sbase + nxt * GEMM_STAGE,
                       Ah, Al, Bh, Bl, row0, col0, (c + 2) * 32, tid);
            CP_COMMIT();
        }
        const uint32_t aBase = sbase + cur * GEMM_STAGE;
        const uint32_t bBase = aBase + 16384;
        cur = (cur == 2) ? 0 : cur + 1;
        nxt = (nxt == 2) ? 0 : nxt + 1;

#pragma unroll
        for (int ks = 0; ks < 2; ks++) {
            uint32_t af[4][4], bhf[4][4], blf[4][4];
#pragma unroll
            for (int mt = 0; mt < 4; mt++) {
                const int r = wm * 64 + mt * 16 + (lid & 15);
                const int lu = ks * 2 + (lid >> 4);
                ldsm_x4(af[mt], aBase + r * 128 + ((lu ^ (r & 7)) * 16));
            }
#pragma unroll
            for (int np = 0; np < 4; np++) {
                const int r  = wn * 64 + np * 16 + ((lid >> 4) & 1) * 8 + (lid & 7);
                const int lu = ks * 2 + ((lid >> 3) & 1);
                ldsm_x4(bhf[np], bBase + r * 128 + ((lu ^ (r & 7)) * 16));
                ldsm_x4(blf[np], bBase + r * 128 + (((lu + 4) ^ (r & 7)) * 16));
            }
#pragma unroll
            for (int mt = 0; mt < 4; mt++)
#pragma unroll
                for (int nt = 0; nt < 8; nt++) {
                    mma16816(acc[mt][nt], af[mt],
                             bhf[nt >> 1][(nt & 1) * 2], bhf[nt >> 1][(nt & 1) * 2 + 1]);
                    mma16816(acc[mt][nt], af[mt],
                             blf[nt >> 1][(nt & 1) * 2], blf[nt >> 1][(nt & 1) * 2 + 1]);
                }
#pragma unroll
            for (int mt = 0; mt < 4; mt++) {
                const int r = wm * 64 + mt * 16 + (lid & 15);
                const int lu = 4 + ks * 2 + (lid >> 4);
                ldsm_x4(af[mt], aBase + r * 128 + ((lu ^ (r & 7)) * 16));
            }
#pragma unroll
            for (int mt = 0; mt < 4; mt++)
#pragma unroll
                for (int nt = 0; nt < 8; nt++)
                    mma16816(acc[mt][nt], af[mt],
                             bhf[nt >> 1][(nt & 1) * 2], bhf[nt >> 1][(nt & 1) * 2 + 1]);
        }
    }

#pragma unroll
    for (int mt = 0; mt < 4; mt++) {
        const int r = row0 + wm * 64 + mt * 16 + (lid >> 2);
#pragma unroll
        for (int nt = 0; nt < 8; nt++) {
            const int cc = col0 + wn * 64 + nt * 8 + (lid & 3) * 2;
            *(float2*)&C[(size_t)r * Ntot + cc] =
                make_float2(acc[mt][nt][0], acc[mt][nt][1]);
            *(float2*)&C[(size_t)(r + 8) * Ntot + cc] =
                make_float2(acc[mt][nt][2], acc[mt][nt][3]);
        }
    }
}

// Fused QKV: blockIdx.x 0..23 (0-15 Q, 16-19 K, 20-23 V)
__global__ void __launch_bounds__(256, 1)
gemm_qkv_kernel(const __nv_bfloat16* __restrict__ xh,
                const __nv_bfloat16* __restrict__ xl,
                const __nv_bfloat16* __restrict__ wqh, const __nv_bfloat16* __restrict__ wql,
                const __nv_bfloat16* __restrict__ wkh, const __nv_bfloat16* __restrict__ wkl,
                const __nv_bfloat16* __restrict__ wvh, const __nv_bfloat16* __restrict__ wvl,
                float* __restrict__ Q, float* __restrict__ K, float* __restrict__ V)
{
    extern __shared__ char smraw[];
    const int xb = blockIdx.x;
    const int row0 = blockIdx.y * 128;
    const __nv_bfloat16 *Bh, *Bl;
    float* C; int Ntot, col0;
    if (xb < 16)      { Bh = wqh; Bl = wql; C = Q; Ntot = DIM;   col0 = xb * 256; }
    else if (xb < 20) { Bh = wkh; Bl = wkl; C = K; Ntot = KVDIM; col0 = (xb - 16) * 256; }
    else              { Bh = wvh; Bl = wvl; C = V; Ntot = KVDIM; col0 = (xb - 20) * 256; }
    gemm_body(xh, xl, Bh, Bl, C, Ntot, row0, col0, smraw);
}

// ---------------------------------------------------------------------------
// fp16 2-pass output projection GEMM (validated R8).
// ---------------------------------------------------------------------------
#define F2_STAGE 65536
#define F2_SMEM  (3 * F2_STAGE + 1024)
#define F2_NC    (DIM / 64)

__device__ __forceinline__ void f2_stage_load(
    uint32_t st, const __half* __restrict__ Yh, const __half* __restrict__ Yl,
    const __half* __restrict__ Wh, int row0, int col0, int k0, int tid)
{
    const int r  = tid >> 1;
    const int h  = tid & 1;
    const int sw = r & 7;
#pragma unroll
    for (int s = 0; s < 2; s++) {
        const __half* src = (h ? Yl : Yh) + (size_t)(row0 + r) * DIM + k0 + s * 32;
        const uint32_t rowp = st + s * 16384 + r * 128;
#pragma unroll
        for (int u = 0; u < 4; u++)
            CP_ASYNC16(rowp + (((h * 4 + u) ^ sw) * 16), src + u * 8);
    }
#pragma unroll
    for (int p = 0; p < 2; p++) {
        const int rb = r + p * 128;
        const int swb = rb & 7;
        const __half* src = Wh + (size_t)(col0 + rb) * DIM + k0 + h * 32;
        const uint32_t rowp = st + 32768 + rb * 128;
#pragma unroll
        for (int u = 0; u < 4; u++)
            CP_ASYNC16(rowp + (((h * 4 + u) ^ swb) * 16), src + u * 8);
    }
}

__global__ void __launch_bounds__(256, 1)
gemm_f16_2p(const __half* __restrict__ Yh, const __half* __restrict__ Yl,
            const __half* __restrict__ Wh, float* __restrict__ C, int Ntot)
{
    extern __shared__ char smraw[];
    const uint32_t sbase = (smem_u32(smraw) + 1023u) & ~1023u;
    const int tid = threadIdx.x;
    const int lid = tid & 31;
    const int wid = tid >> 5;
    const int wm  = wid & 1;
    const int wn  = wid >> 1;
    const int row0 = blockIdx.y * 128;
    const int col0 = blockIdx.x * 256;

    float acc[4][8][4];
#pragma unroll
    for (int i = 0; i < 4; i++)
#pragma unroll
        for (int j = 0; j < 8; j++)
#pragma unroll
            for (int q = 0; q < 4; q++) acc[i][j][q] = 0.f;

    f2_stage_load(sbase,            Yh, Yl, Wh, row0, col0, 0,  tid);
    CP_COMMIT();
    f2_stage_load(sbase + F2_STAGE, Yh, Yl, Wh, row0, col0, 64, tid);
    CP_COMMIT();

    int cur = 0, nxt = 2;
    for (int c = 0; c < F2_NC; c++) {
        CP_WAIT1();
        __syncthreads();
        if (c + 2 < F2_NC) {
            f2_stage_load(sbase + nxt * F2_STAGE,
                          Yh, Yl, Wh, row0, col0, (c + 2) * 64, tid);
            CP_COMMIT();
        }
        const uint32_t aBase = sbase + cur * F2_STAGE;
        const uint32_t bBase = aBase + 32768;
        cur = (cur == 2) ? 0 : cur + 1;
        nxt = (nxt == 2) ? 0 : nxt + 1;

#pragma unroll
        for (int ks = 0; ks < 4; ks++) {
            const int sub = ks >> 1;
            uint32_t ahf[4][4], alf[4][4], bf[4][4];
#pragma unroll
            for (int mt = 0; mt < 4; mt++) {
                const int r = wm * 64 + mt * 16 + (lid & 15);
                const int luh = (ks & 1) * 2 + (lid >> 4);
                const uint32_t rowp = aBase + sub * 16384 + r * 128;
                ldsm_x4(ahf[mt], rowp + ((luh ^ (r & 7)) * 16));
                ldsm_x4(alf[mt], rowp + (((luh + 4) ^ (r & 7)) * 16));
            }
#pragma unroll
            for (int np = 0; np < 4; np++) {
                const int r  = wn * 64 + np * 16 + ((lid >> 4) & 1) * 8 + (lid & 7);
                const int lu = ks * 2 + ((lid >> 3) & 1);
                ldsm_x4(bf[np], bBase + r * 128 + ((lu ^ (r & 7)) * 16));
            }
#pragma unroll
            for (int mt = 0; mt < 4; mt++)
#pragma unroll
                for (int nt = 0; nt < 8; nt++) {
                    mma16816h(acc[mt][nt], ahf[mt],
                              bf[nt >> 1][(nt & 1) * 2], bf[nt >> 1][(nt & 1) * 2 + 1]);
                    mma16816h(acc[mt][nt], alf[mt],
                              bf[nt >> 1][(nt & 1) * 2], bf[nt >> 1][(nt & 1) * 2 + 1]);
                }
        }
    }

#pragma unroll
    for (int mt = 0; mt < 4; mt++) {
        const int r = row0 + wm * 64 + mt * 16 + (lid >> 2);
#pragma unroll
        for (int nt = 0; nt < 8; nt++) {
            const int cc = col0 + wn * 64 + nt * 8 + (lid & 3) * 2;
            *(float2*)&C[(size_t)r * Ntot + cc] =
                make_float2(acc[mt][nt][0], acc[mt][nt][1]);
            *(float2*)&C[(size_t)(r + 8) * Ntot + cc] =
                make_float2(acc[mt][nt][2], acc[mt][nt][3]);
        }
    }
}

// ---------------------------------------------------------------------------
// fp16 single-pass flash attention. Br=128 (8 warps), Bc=64, causal, GQA 4.
// S = Q16.K16 (1 MMA); O = P16.V16 (1 MMA).
// smem: Q 32K | 2 stages x (K 16K; Vt 16K) = 96K.
// ---------------------------------------------------------------------------
#define AT_Q 0
#define AT_ST(b) (32768 + (b) * 32768)
#define AT_K 0
#define AT_V 16384
#define AT_SMEM (32768 + 2 * 32768)

__device__ __forceinline__ void attn_load_kv(
    uint32_t stage, const __half* __restrict__ K16,
    const __half* __restrict__ Vt16, int j, int kvh, int tid)
{
    for (int idx = tid; idx < 1024; idx += 256) {
        const int r = idx >> 4, u = idx & 15;
        const int phys = ((u ^ (r & 7)) * 16);
        const size_t gk = ((size_t)(j * 64 + r) * NKV + kvh) * HD + u * 8;
        CP_ASYNC16(stage + AT_K + r * 256 + phys, K16 + gk);
    }
    for (int idx = tid; idx < 1024; idx += 256) {
        const int r = idx >> 3, u = idx & 7;
        const int phys = ((u ^ (r & 7)) * 16);
        const size_t gv = ((size_t)(kvh * 128 + r)) * SEQ + j * 64 + u * 8;
        CP_ASYNC16(stage + AT_V + r * 128 + phys, Vt16 + gv);
    }
}

__global__ void __launch_bounds__(256)
attn_f16_kernel(const __half* __restrict__ Q16,
                const __half* __restrict__ K16,
                const __half* __restrict__ Vt16,
                __half* __restrict__ Yh, __half* __restrict__ Yl)
{
    extern __shared__ char smraw[];
    const uint32_t sb = smem_u32(smraw);

    const int qt  = blockIdx.x;
    const int h   = blockIdx.y;
    const int kvh = h >> 2;
    const int tid = threadIdx.x;
    const int lid = tid & 31;
    const int wid = tid >> 5;
    const int qrow0 = qt * 128;

    // Q tile (128 x 128 fp16)
    for (int idx = tid; idx < 2048; idx += 256) {
        const int r = idx >> 4, u = idx & 15;
        const int phys = ((u ^ (r & 7)) * 16);
        const size_t g = ((size_t)(qrow0 + r) * NH + h) * HD + u * 8;
        CP_ASYNC16(sb + AT_Q + r * 256 + phys, Q16 + g);
    }
    attn_load_kv(sb + AT_ST(0), K16, Vt16, 0, kvh, tid);
    CP_COMMIT();

    float o[16][4];
#pragma unroll
    for (int dt = 0; dt < 16; dt++)
#pragma unroll
        for (int q = 0; q < 4; q++) o[dt][q] = 0.f;
    float mA = -1e30f, mB = -1e30f, lA = 0.f, lB = 0.f;

    const int g  = lid >> 2;
    const int cA = (lid & 3) * 2;
    const int jEnd = 2 * qt + 1;

    for (int j = 0; j <= jEnd; j++) {
        CP_WAIT0();
        __syncthreads();
        if (j < jEnd) {
            attn_load_kv(sb + AT_ST((j + 1) & 1), K16, Vt16, j + 1, kvh, tid);
            CP_COMMIT();
        }
        const uint32_t kb = sb + AT_ST(j & 1);

        // ---- S = Q K^T (single fp16 pass) ----
        float s[8][4];
#pragma unroll
        for (int nt = 0; nt < 8; nt++)
#pragma unroll
            for (int q = 0; q < 4; q++) s[nt][q] = 0.f;

#pragma unroll
        for (int kc = 0; kc < 8; kc++) {
            uint32_t qf[4];
            const int rA = wid * 16 + (lid & 15);
            const int uA = kc * 2 + (lid >> 4);
            ldsm_x4(qf, sb + AT_Q + rA * 256 + ((uA ^ (rA & 7)) * 16));
#pragma unroll
            for (int np = 0; np < 4; np++) {
                uint32_t kf[4];
                const int rB = np * 16 + ((lid >> 4) & 1) * 8 + (lid & 7);
                const int uB = kc * 2 + ((lid >> 3) & 1);
                ldsm_x4(kf, kb + AT_K + rB * 256 + ((uB ^ (rB & 7)) * 16));
#pragma unroll
                for (int hf = 0; hf < 2; hf++)
                    mma16816h(s[np * 2 + hf], qf, kf[hf * 2], kf[hf * 2 + 1]);
            }
        }

        // ---- causal mask ----
        if (j >= 2 * qt) {
            const int rowA = qrow0 + wid * 16 + g;
            const int colBase = j * 64;
#pragma unroll
            for (int nt = 0; nt < 8; nt++) {
                const int col = colBase + nt * 8 + cA;
                if (col     > rowA)     s[nt][0] = -1e30f;
                if (col + 1 > rowA)     s[nt][1] = -1e30f;
                if (col     > rowA + 8) s[nt][2] = -1e30f;
                if (col + 1 > rowA + 8) s[nt][3] = -1e30f;
            }
        }

        // ---- online softmax ----
        float mxA = -1e30f, mxB = -1e30f;
#pragma unroll
        for (int nt = 0; nt < 8; nt++) {
            mxA = fmaxf(mxA, fmaxf(s[nt][0], s[nt][1]));
            mxB = fmaxf(mxB, fmaxf(s[nt][2], s[nt][3]));
        }
        mxA = fmaxf(mxA, __shfl_xor_sync(0xffffffffu, mxA, 1));
        mxA = fmaxf(mxA, __shfl_xor_sync(0xffffffffu, mxA, 2));
        mxB = fmaxf(mxB, __shfl_xor_sync(0xffffffffu, mxB, 1));
        mxB = fmaxf(mxB, __shfl_xor_sync(0xffffffffu, mxB, 2));
        const float mnA = fmaxf(mA, mxA), mnB = fmaxf(mB, mxB);
        const float alA = __expf(mA - mnA), alB = __expf(mB - mnB);

        uint32_t p[8][2];
        float rsA = 0.f, rsB = 0.f;
#pragma unroll
        for (int nt = 0; nt < 8; nt++) {
            float p0 = __expf(s[nt][0] - mnA);
            float p1 = __expf(s[nt][1] - mnA);
            float p2 = __expf(s[nt][2] - mnB);
            float p3 = __expf(s[nt][3] - mnB);
            rsA += p0 + p1;  rsB += p2 + p3;
            __half2 a0 = __floats2half2_rn(p0, p1);
            __half2 a1 = __floats2half2_rn(p2, p3);
            p[nt][0] = *reinterpret_cast<uint32_t*>(&a0);
            p[nt][1] = *reinterpret_cast<uint32_t*>(&a1);
        }
        rsA += __shfl_xor_sync(0xffffffffu, rsA, 1);
        rsA += __shfl_xor_sync(0xffffffffu, rsA, 2);
        rsB += __shfl_xor_sync(0xffffffffu, rsB, 1);
        rsB += __shfl_xor_sync(0xffffffffu, rsB, 2);
        lA = lA * alA + rsA;  mA = mnA;
        lB = lB * alB + rsB;  mB = mnB;

#pragma unroll
        for (int dt = 0; dt < 16; dt++) {
            o[dt][0] *= alA; o[dt][1] *= alA;
            o[dt][2] *= alB; o[dt][3] *= alB;
        }

        // ---- O += P V (single fp16 pass) ----
#pragma unroll
        for (int kc = 0; kc < 4; kc++) {
            uint32_t a[4] = { p[2 * kc][0], p[2 * kc][1],
                              p[2 * kc + 1][0], p[2 * kc + 1][1] };
#pragma unroll
            for (int dp = 0; dp < 8; dp++) {
                uint32_t vf[4];
                const int rB = dp * 16 + ((lid >> 4) & 1) * 8 + (lid & 7);
                const int uB = kc * 2 + ((lid >> 3) & 1);
                ldsm_x4(vf, kb + AT_V + rB * 128 + ((uB ^ (rB & 7)) * 16));
#pragma unroll
                for (int hf = 0; hf < 2; hf++)
                    mma16816h(o[dp * 2 + hf], a, vf[hf * 2], vf[hf * 2 + 1]);
            }
        }
    }

    // Epilogue: Y as fp16 hi/lo
    const float invA = 1.f / lA, invB = 1.f / lB;
    const int rowA = qrow0 + wid * 16 + g;
#pragma unroll
    for (int dt = 0; dt < 16; dt++) {
        const int d = h * HD + dt * 8 + cA;
        {
            float v0 = o[dt][0] * invA, v1 = o[dt][1] * invA;
            __half h0 = __float2half_rn(v0), h1 = __float2half_rn(v1);
            __half l0 = __float2half_rn(v0 - __half2float(h0));
            __half l1 = __float2half_rn(v1 - __half2float(h1));
            *(__half2*)&Yh[(size_t)rowA * DIM + d] = __halves2half2(h0, h1);
            *(__half2*)&Yl[(size_t)rowA * DIM + d] = __halves2half2(l0, l1);
        }
        {
            float v0 = o[dt][2] * invB, v1 = o[dt][3] * invB;
            __half h0 = __float2half_rn(v0), h1 = __float2half_rn(v1);
            __half l0 = __float2half_rn(v0 - __half2float(h0));
            __half l1 = __float2half_rn(v1 - __half2float(h1));
            *(__half2*)&Yh[(size_t)(rowA + 8) * DIM + d] = __halves2half2(h0, h1);
            *(__half2*)&Yl[(size_t)(rowA + 8) * DIM + d] = __halves2half2(l0, l1);
        }
    }
}

// ---------------------------------------------------------------------------
// Launch
// ---------------------------------------------------------------------------
extern "C" void kernel_launch(void* const* d_in, const int* in_sizes, int n_in,
                              void* d_out, int out_size)
{
    const float* x  = (const float*)d_in[0];
    const float* fc = (const float*)d_in[1];
    const float* wq = (const float*)d_in[3];
    const float* wk = (const float*)d_in[4];
    const float* wv = (const float*)d_in[5];
    const float* wo = (const float*)d_in[6];
    float* out = (float*)d_out;

    float *Q, *Kp, *Vp;
    cudaGetSymbolAddress((void**)&Q,  g_q);
    cudaGetSymbolAddress((void**)&Kp, g_k);
    cudaGetSymbolAddress((void**)&Vp, g_v);

    __nv_bfloat16 *xh, *xl, *wqh, *wql, *wkh, *wkl, *wvh, *wvl;
    __half *wo16, *yh16, *yl16, *q16, *k16, *vt16;
    cudaGetSymbolAddress((void**)&xh,  g_xh);  cudaGetSymbolAddress((void**)&xl,  g_xl);
    cudaGetSymbolAddress((void**)&wqh, g_wqh); cudaGetSymbolAddress((void**)&wql, g_wql);
    cudaGetSymbolAddress((void**)&wkh, g_wkh); cudaGetSymbolAddress((void**)&wkl, g_wkl);
    cudaGetSymbolAddress((void**)&wvh, g_wvh); cudaGetSymbolAddress((void**)&wvl, g_wvl);
    cudaGetSymbolAddress((void**)&wo16, g_wo16);
    cudaGetSymbolAddress((void**)&yh16, g_yh16);
    cudaGetSymbolAddress((void**)&yl16, g_yl16);
    cudaGetSymbolAddress((void**)&q16,  g_q16);
    cudaGetSymbolAddress((void**)&k16,  g_k16);
    cudaGetSymbolAddress((void**)&vt16, g_vt16);

    cudaFuncSetAttribute(gemm_qkv_kernel,
                         cudaFuncAttributeMaxDynamicSharedMemorySize, GEMM_SMEM);
    cudaFuncSetAttribute(gemm_f16_2p,
                         cudaFuncAttributeMaxDynamicSharedMemorySize, F2_SMEM);
    cudaFuncSetAttribute(attn_f16_kernel,
                         cudaFuncAttributeMaxDynamicSharedMemorySize, AT_SMEM);

    const int T = 256;
    split_kernel<<<(SEQ * DIM / 8 + T - 1) / T, T>>>(x,  xh,  xl,  SEQ * DIM / 8);
    split_kernel<<<(DIM * DIM / 8 + T - 1) / T, T>>>(wq, wqh, wql, DIM * DIM / 8);
    split_kernel<<<(KVDIM * DIM / 8 + T - 1) / T, T>>>(wk, wkh, wkl, KVDIM * DIM / 8);
    split_kernel<<<(KVDIM * DIM / 8 + T - 1) / T, T>>>(wv, wvh, wvl, KVDIM * DIM / 8);
    trunc16_kernel<<<(DIM * DIM / 8 + T - 1) / T, T>>>(wo, wo16, DIM * DIM / 8);

    // Fused QKV projection (bf16 3-pass)
    gemm_qkv_kernel<<<dim3(24, SEQ / 128), 256, GEMM_SMEM>>>(
        xh, xl, wqh, wql, wkh, wkl, wvh, wvl, Q, Kp, Vp);

    // RoPE -> fp16; V transpose -> fp16
    const float scale = 0.08838834764831845f;
    rope_f16_kernel<<<(SEQ * NH  * 64 + T - 1) / T, T>>>(
        Q,  fc, q16, NH,  scale, SEQ * NH  * 64);
    rope_f16_kernel<<<(SEQ * NKV * 64 + T - 1) / T, T>>>(
        Kp, fc, k16, NKV, 1.0f,  SEQ * NKV * 64);
    vt_f16_kernel<<<(KVDIM * SEQ + T - 1) / T, T>>>(Vp, vt16);

    // Attention (fp16 single-pass QK and PV)
    attn_f16_kernel<<<dim3(SEQ / 128, NH), 256, AT_SMEM>>>(
        q16, k16, vt16, yh16, yl16);

    // Output projection (fp16 2-pass)
    gemm_f16_2p<<<dim3(DIM / 256, SEQ / 128), 256, F2_SMEM>>>(
        yh16, yl16, wo16, out, DIM);
}

// round 11
// speedup vs baseline: 3.8013x; 1.6222x over previous
#include <cuda_runtime.h>
#include <cuda_bf16.h>
#include <cuda_fp16.h>
#include <math.h>
#include <stdint.h>

#define SEQ    2048
#define DIM    4096
#define NH     32
#define NKV    8
#define HD     128
#define KVDIM  (NKV*HD)

// ---------------------------------------------------------------------------
// Scratch (device globals)
// ---------------------------------------------------------------------------
static __device__ float g_q[SEQ * DIM];
static __device__ float g_k[SEQ * KVDIM];
static __device__ float g_v[SEQ * KVDIM];

static __device__ __half g_xh16[SEQ * DIM], g_xl16[SEQ * DIM];   // X two-level fp16
static __device__ __half g_wq16[DIM * DIM];
static __device__ __half g_wk16[KVDIM * DIM];
static __device__ __half g_wv16[KVDIM * DIM];
static __device__ __half g_wo16[DIM * DIM];
static __device__ __half g_yh16[SEQ * DIM];

static __device__ __half g_q16[SEQ * DIM];
static __device__ __half g_k16[SEQ * KVDIM];
static __device__ __half g_vt16[KVDIM * SEQ];   // [kvh*128+d][s]

// ---------------------------------------------------------------------------
// Helpers
// ---------------------------------------------------------------------------
__device__ __forceinline__ uint32_t smem_u32(const void* p) {
    uint32_t a;
    asm("{ .reg .u64 t; cvta.to.shared.u64 t, %1; cvt.u32.u64 %0, t; }"
        : "=r"(a) : "l"(p));
    return a;
}

__device__ __forceinline__ void ldsm_x4(uint32_t* d, uint32_t addr) {
    asm volatile("ldmatrix.sync.aligned.m8n8.x4.shared.b16 {%0,%1,%2,%3}, [%4];"
                 : "=r"(d[0]), "=r"(d[1]), "=r"(d[2]), "=r"(d[3]) : "r"(addr));
}

__device__ __forceinline__ void mma16816h(float* c, const uint32_t* a,
                                          uint32_t b0, uint32_t b1) {
    asm volatile(
        "mma.sync.aligned.m16n8k16.row.col.f32.f16.f16.f32 "
        "{%0,%1,%2,%3}, {%4,%5,%6,%7}, {%8,%9}, {%0,%1,%2,%3};"
        : "+f"(c[0]), "+f"(c[1]), "+f"(c[2]), "+f"(c[3])
        : "r"(a[0]), "r"(a[1]), "r"(a[2]), "r"(a[3]), "r"(b0), "r"(b1));
}

#define CP_ASYNC16(dst, src) \
    asm volatile("cp.async.cg.shared.global [%0], [%1], 16;" :: "r"(dst), "l"(src))
#define CP_COMMIT() asm volatile("cp.async.commit_group;" ::: "memory")
#define CP_WAIT0()  asm volatile("cp.async.wait_group 0;"  ::: "memory")
#define CP_WAIT1()  asm volatile("cp.async.wait_group 1;"  ::: "memory")

// ---------------------------------------------------------------------------
// Pointwise kernels
// ---------------------------------------------------------------------------
__global__ void split16_kernel(const float* __restrict__ in,
                               __half* __restrict__ hi,
                               __half* __restrict__ lo, int n8)
{
    int i = blockIdx.x * blockDim.x + threadIdx.x;
    if (i >= n8) return;
#pragma unroll
    for (int half = 0; half < 2; half++) {
        float4 v = ((const float4*)in)[2 * i + half];
        float vv[4] = {v.x, v.y, v.z, v.w};
        __half h[4], l[4];
#pragma unroll
        for (int e = 0; e < 4; e++) {
            h[e] = __float2half_rn(vv[e]);
            l[e] = __float2half_rn(vv[e] - __half2float(h[e]));
        }
        __half2* hp = (__half2*)hi;
        __half2* lp = (__half2*)lo;
        hp[4 * i + 2 * half]     = __halves2half2(h[0], h[1]);
        hp[4 * i + 2 * half + 1] = __halves2half2(h[2], h[3]);
        lp[4 * i + 2 * half]     = __halves2half2(l[0], l[1]);
        lp[4 * i + 2 * half + 1] = __halves2half2(l[2], l[3]);
    }
}

__global__ void trunc16_kernel(const float* __restrict__ in,
                               __half* __restrict__ out, int n8)
{
    int i = blockIdx.x * blockDim.x + threadIdx.x;
    if (i >= n8) return;
#pragma unroll
    for (int half = 0; half < 2; half++) {
        float4 v = ((const float4*)in)[2 * i + half];
        __half2* op = (__half2*)out;
        op[4 * i + 2 * half]     = __floats2half2_rn(v.x, v.y);
        op[4 * i + 2 * half + 1] = __floats2half2_rn(v.z, v.w);
    }
}

__global__ void rope_f16_kernel(const float* __restrict__ x,
                                const float* __restrict__ fc,
                                __half* __restrict__ o,
                                int nheads, float scale, int total)
{
    int idx = blockIdx.x * blockDim.x + threadIdx.x;
    if (idx >= total) return;
    const int i = idx & 63;
    const int h = (idx >> 6) % nheads;
    const int s = idx / (64 * nheads);
    const float c  = fc[(s * 64 + i) * 2 + 0];
    const float sn = fc[(s * 64 + i) * 2 + 1];
    const size_t off = ((size_t)s * nheads + h) * HD + 2 * i;
    float2 v = *(const float2*)(x + off);
    float a = (v.x * c - v.y * sn) * scale;
    float b = (v.y * c + v.x * sn) * scale;
    *(__half2*)(o + off) = __floats2half2_rn(a, b);
}

__global__ void vt_f16_kernel(const float* __restrict__ v,
                              __half* __restrict__ vt)
{
    int idx = blockIdx.x * blockDim.x + threadIdx.x;
    const int s = idx & (SEQ - 1);
    const int dl = idx >> 11;
    if (dl >= KVDIM) return;
    vt[idx] = __float2half_rn(v[(size_t)s * KVDIM + dl]);
}

// ---------------------------------------------------------------------------
// fp16 2-pass GEMM body: C = Ah@B^T + Al@B^T, fp32 accum.
// CTA tile 128x256, 8 warps (2x4), K-chunk 64, 3-stage cp.async.
// Stage 64KB: A sub0 16K | A sub1 16K | B 32K.
// A row (128B): [hi 32 f16 | lo 32 f16]; B row (128B): 64 f16.
// ---------------------------------------------------------------------------
#define F2_STAGE 65536
#define F2_SMEM  (3 * F2_STAGE + 1024)
#define F2_NC    (DIM / 64)

__device__ __forceinline__ void f2_stage_load(
    uint32_t st, const __half* __restrict__ Ah, const __half* __restrict__ Al,
    const __half* __restrict__ B, int row0, int col0, int k0, int tid)
{
    const int r  = tid >> 1;
    const int h  = tid & 1;
    const int sw = r & 7;
#pragma unroll
    for (int s = 0; s < 2; s++) {
        const __half* src = (h ? Al : Ah) + (size_t)(row0 + r) * DIM + k0 + s * 32;
        const uint32_t rowp = st + s * 16384 + r * 128;
#pragma unroll
        for (int u = 0; u < 4; u++)
            CP_ASYNC16(rowp + (((h * 4 + u) ^ sw) * 16), src + u * 8);
    }
#pragma unroll
    for (int p = 0; p < 2; p++) {
        const int rb = r + p * 128;
        const int swb = rb & 7;
        const __half* src = B + (size_t)(col0 + rb) * DIM + k0 + h * 32;
        const uint32_t rowp = st + 32768 + rb * 128;
#pragma unroll
        for (int u = 0; u < 4; u++)
            CP_ASYNC16(rowp + (((h * 4 + u) ^ swb) * 16), src + u * 8);
    }
}

__device__ __forceinline__ void gemm_f16_2p_body(
    const __half* __restrict__ Ah, const __half* __restrict__ Al,
    const __half* __restrict__ B, float* __restrict__ C, int Ntot,
    int row0, int col0, char* smraw)
{
    const uint32_t sbase = (smem_u32(smraw) + 1023u) & ~1023u;
    const int tid = threadIdx.x;
    const int lid = tid & 31;
    const int wid = tid >> 5;
    const int wm  = wid & 1;
    const int wn  = wid >> 1;

    float acc[4][8][4];
#pragma unroll
    for (int i = 0; i < 4; i++)
#pragma unroll
        for (int j = 0; j < 8; j++)
#pragma unroll
            for (int q = 0; q < 4; q++) acc[i][j][q] = 0.f;

    f2_stage_load(sbase,            Ah, Al, B, row0, col0, 0,  tid);
    CP_COMMIT();
    f2_stage_load(sbase + F2_STAGE, Ah, Al, B, row0, col0, 64, tid);
    CP_COMMIT();

    int cur = 0, nxt = 2;
    for (int c = 0; c < F2_NC; c++) {
        CP_WAIT1();
        __syncthreads();
        if (c + 2 < F2_NC) {
            f2_stage_load(sbase + nxt * F2_STAGE,
                          Ah, Al, B, row0, col0, (c + 2) * 64, tid);
            CP_COMMIT();
        }
        const uint32_t aBase = sbase + cur * F2_STAGE;
        const uint32_t bBase = aBase + 32768;
        cur = (cur == 2) ? 0 : cur + 1;
        nxt = (nxt == 2) ? 0 : nxt + 1;

#pragma unroll
        for (int ks = 0; ks < 4; ks++) {
            const int sub = ks >> 1;
            uint32_t ahf[4][4], alf[4][4], bf[4][4];
#pragma unroll
            for (int mt = 0; mt < 4; mt++) {
                const int r = wm * 64 + mt * 16 + (lid & 15);
                const int luh = (ks & 1) * 2 + (lid >> 4);
                const uint32_t rowp = aBase + sub * 16384 + r * 128;
                ldsm_x4(ahf[mt], rowp + ((luh ^ (r & 7)) * 16));
                ldsm_x4(alf[mt], rowp + (((luh + 4) ^ (r & 7)) * 16));
            }
#pragma unroll
            for (int np = 0; np < 4; np++) {
                const int r  = wn * 64 + np * 16 + ((lid >> 4) & 1) * 8 + (lid & 7);
                const int lu = ks * 2 + ((lid >> 3) & 1);
                ldsm_x4(bf[np], bBase + r * 128 + ((lu ^ (r & 7)) * 16));
            }
#pragma unroll
            for (int mt = 0; mt < 4; mt++)
#pragma unroll
                for (int nt = 0; nt < 8; nt++) {
                    mma16816h(acc[mt][nt], ahf[mt],
                              bf[nt >> 1][(nt & 1) * 2], bf[nt >> 1][(nt & 1) * 2 + 1]);
                    mma16816h(acc[mt][nt], alf[mt],
                              bf[nt >> 1][(nt & 1) * 2], bf[nt >> 1][(nt & 1) * 2 + 1]);
                }
        }
    }

#pragma unroll
    for (int mt = 0; mt < 4; mt++) {
        const int r = row0 + wm * 64 + mt * 16 + (lid >> 2);
#pragma unroll
        for (int nt = 0; nt < 8; nt++) {
            const int cc = col0 + wn * 64 + nt * 8 + (lid & 3) * 2;
            *(float2*)&C[(size_t)r * Ntot + cc] =
                make_float2(acc[mt][nt][0], acc[mt][nt][1]);
            *(float2*)&C[(size_t)(r + 8) * Ntot + cc] =
                make_float2(acc[mt][nt][2], acc[mt][nt][3]);
        }
    }
}

// Fused QKV (fp16 2-pass): blockIdx.x 0..23 (0-15 Q, 16-19 K, 20-23 V)
__global__ void __launch_bounds__(256, 1)
gemm_qkv16(const __half* __restrict__ xh, const __half* __restrict__ xl,
           const __half* __restrict__ wq16, const __half* __restrict__ wk16,
           const __half* __restrict__ wv16,
           float* __restrict__ Q, float* __restrict__ K, float* __restrict__ V)
{
    extern __shared__ char smraw[];
    const int xb = blockIdx.x;
    const int row0 = blockIdx.y * 128;
    const __half* B; float* C; int Ntot, col0;
    if (xb < 16)      { B = wq16; C = Q; Ntot = DIM;   col0 = xb * 256; }
    else if (xb < 20) { B = wk16; C = K; Ntot = KVDIM; col0 = (xb - 16) * 256; }
    else              { B = wv16; C = V; Ntot = KVDIM; col0 = (xb - 20) * 256; }
    gemm_f16_2p_body(xh, xl, B, C, Ntot, row0, col0, smraw);
}

// ---------------------------------------------------------------------------
// fp16 1-pass GEMM (output projection): C = Yh @ Wo^T.
// CTA tile 128x256, K-chunk 64. Stage 48KB: A 16K | B 32K.
// ---------------------------------------------------------------------------
#define F1_STAGE 49152
#define F1_SMEM  (3 * F1_STAGE + 1024)
#define F1_NC    (DIM / 64)

__device__ __forceinline__ void f1_stage_load(
    uint32_t st, const __half* __restrict__ A, const __half* __restrict__ B,
    int row0, int col0, int k0, int tid)
{
    const int r  = tid >> 1;
    const int h  = tid & 1;
    const int sw = r & 7;
    {
        const __half* src = A + (size_t)(row0 + r) * DIM + k0 + h * 32;
        const uint32_t rowp = st + r * 128;
#pragma unroll
        for (int u = 0; u < 4; u++)
            CP_ASYNC16(rowp + (((h * 4 + u) ^ sw) * 16), src + u * 8);
    }
#pragma unroll
    for (int p = 0; p < 2; p++) {
        const int rb = r + p * 128;
        const int swb = rb & 7;
        const __half* src = B + (size_t)(col0 + rb) * DIM + k0 + h * 32;
        const uint32_t rowp = st + 16384 + rb * 128;
#pragma unroll
        for (int u = 0; u < 4; u++)
            CP_ASYNC16(rowp + (((h * 4 + u) ^ swb) * 16), src + u * 8);
    }
}

__global__ void __launch_bounds__(256, 1)
gemm_f16_1p(const __half* __restrict__ Yh, const __half* __restrict__ Wo,
            float* __restrict__ C, int Ntot)
{
    extern __shared__ char smraw[];
    const uint32_t sbase = (smem_u32(smraw) + 1023u) & ~1023u;
    const int tid = threadIdx.x;
    const int lid = tid & 31;
    const int wid = tid >> 5;
    const int wm  = wid & 1;
    const int wn  = wid >> 1;
    const int row0 = blockIdx.y * 128;
    const int col0 = blockIdx.x * 256;

    float acc[4][8][4];
#pragma unroll
    for (int i = 0; i < 4; i++)
#pragma unroll
        for (int j = 0; j < 8; j++)
#pragma unroll
            for (int q = 0; q < 4; q++) acc[i][j][q] = 0.f;

    f1_stage_load(sbase,            Yh, Wo, row0, col0, 0,  tid);
    CP_COMMIT();
    f1_stage_load(sbase + F1_STAGE, Yh, Wo, row0, col0, 64, tid);
    CP_COMMIT();

    int cur = 0, nxt = 2;
    for (int c = 0; c < F1_NC; c++) {
        CP_WAIT1();
        __syncthreads();
        if (c + 2 < F1_NC) {
            f1_stage_load(sbase + nxt * F1_STAGE,
                          Yh, Wo, row0, col0, (c + 2) * 64, tid);
            CP_COMMIT();
        }
        const uint32_t aBase = sbase + cur * F1_STAGE;
        const uint32_t bBase = aBase + 16384;
        cur = (cur == 2) ? 0 : cur + 1;
        nxt = (nxt == 2) ? 0 : nxt + 1;

#pragma unroll
        for (int ks = 0; ks < 4; ks++) {
            uint32_t af[4][4], bf[4][4];
#pragma unroll
            for (int mt = 0; mt < 4; mt++) {
                const int r = wm * 64 + mt * 16 + (lid & 15);
                const int lu = ks * 2 + (lid >> 4);
                ldsm_x4(af[mt], aBase + r * 128 + ((lu ^ (r & 7)) * 16));
            }
#pragma unroll
            for (int np = 0; np < 4; np++) {
                const int r  = wn * 64 + np * 16 + ((lid >> 4) & 1) * 8 + (lid & 7);
                const int lu = ks * 2 + ((lid >> 3) & 1);
                ldsm_x4(bf[np], bBase + r * 128 + ((lu ^ (r & 7)) * 16));
            }
#pragma unroll
            for (int mt = 0; mt < 4; mt++)
#pragma unroll
                for (int nt = 0; nt < 8; nt++)
                    mma16816h(acc[mt][nt], af[mt],
                              bf[nt >> 1][(nt & 1) * 2], bf[nt >> 1][(nt & 1) * 2 + 1]);
        }
    }

#pragma unroll
    for (int mt = 0; mt < 4; mt++) {
        const int r = row0 + wm * 64 + mt * 16 + (lid >> 2);
#pragma unroll
        for (int nt = 0; nt < 8; nt++) {
            const int cc = col0 + wn * 64 + nt * 8 + (lid & 3) * 2;
            *(float2*)&C[(size_t)r * Ntot + cc] =
                make_float2(acc[mt][nt][0], acc[mt][nt][1]);
            *(float2*)&C[(size_t)(r + 8) * Ntot + cc] =
                make_float2(acc[mt][nt][2], acc[mt][nt][3]);
        }
    }
}

// ---------------------------------------------------------------------------
// fp16 single-pass flash attention (validated R9). Br=128, Bc=64, causal.
// Epilogue writes only Yh (fp16).
// ---------------------------------------------------------------------------
#define AT_Q 0
#define AT_ST(b) (32768 + (b) * 32768)
#define AT_K 0
#define AT_V 16384
#define AT_SMEM (32768 + 2 * 32768)

__device__ __forceinline__ void attn_load_kv(
    uint32_t stage, const __half* __restrict__ K16,
    const __half* __restrict__ Vt16, int j, int kvh, int tid)
{
    for (int idx = tid; idx < 1024; idx += 256) {
        const int r = idx >> 4, u = idx & 15;
        const int phys = ((u ^ (r & 7)) * 16);
        const size_t gk = ((size_t)(j * 64 + r) * NKV + kvh) * HD + u * 8;
        CP_ASYNC16(stage + AT_K + r * 256 + phys, K16 + gk);
    }
    for (int idx = tid; idx < 1024; idx += 256) {
        const int r = idx >> 3, u = idx & 7;
        const int phys = ((u ^ (r & 7)) * 16);
        const size_t gv = ((size_t)(kvh * 128 + r)) * SEQ + j * 64 + u * 8;
        CP_ASYNC16(stage + AT_V + r * 128 + phys, Vt16 + gv);
    }
}

__global__ void __launch_bounds__(256)
attn_f16_kernel(const __half* __restrict__ Q16,
                const __half* __restrict__ K16,
                const __half* __restrict__ Vt16,
                __half* __restrict__ Yh)
{
    extern __shared__ char smraw[];
    const uint32_t sb = smem_u32(smraw);

    const int qt  = blockIdx.x;
    const int h   = blockIdx.y;
    const int kvh = h >> 2;
    const int tid = threadIdx.x;
    const int lid = tid & 31;
    const int wid = tid >> 5;
    const int qrow0 = qt * 128;

    for (int idx = tid; idx < 2048; idx += 256) {
        const int r = idx >> 4, u = idx & 15;
        const int phys = ((u ^ (r & 7)) * 16);
        const size_t g = ((size_t)(qrow0 + r) * NH + h) * HD + u * 8;
        CP_ASYNC16(sb + AT_Q + r * 256 + phys, Q16 + g);
    }
    attn_load_kv(sb + AT_ST(0), K16, Vt16, 0, kvh, tid);
    CP_COMMIT();

    float o[16][4];
#pragma unroll
    for (int dt = 0; dt < 16; dt++)
#pragma unroll
        for (int q = 0; q < 4; q++) o[dt][q] = 0.f;
    float mA = -1e30f, mB = -1e30f, lA = 0.f, lB = 0.f;

    const int g  = lid >> 2;
    const int cA = (lid & 3) * 2;
    const int jEnd = 2 * qt + 1;

    for (int j = 0; j <= jEnd; j++) {
        CP_WAIT0();
        __syncthreads();
        if (j < jEnd) {
            attn_load_kv(sb + AT_ST((j + 1) & 1), K16, Vt16, j + 1, kvh, tid);
            CP_COMMIT();
        }
        const uint32_t kb = sb + AT_ST(j & 1);

        float s[8][4];
#pragma unroll
        for (int nt = 0; nt < 8; nt++)
#pragma unroll
            for (int q = 0; q < 4; q++) s[nt][q] = 0.f;

#pragma unroll
        for (int kc = 0; kc < 8; kc++) {
            uint32_t qf[4];
            const int rA = wid * 16 + (lid & 15);
            const int uA = kc * 2 + (lid >> 4);
            ldsm_x4(qf, sb + AT_Q + rA * 256 + ((uA ^ (rA & 7)) * 16));
#pragma unroll
            for (int np = 0; np < 4; np++) {
                uint32_t kf[4];
                const int rB = np * 16 + ((lid >> 4) & 1) * 8 + (lid & 7);
                const int uB = kc * 2 + ((lid >> 3) & 1);
                ldsm_x4(kf, kb + AT_K + rB * 256 + ((uB ^ (rB & 7)) * 16));
#pragma unroll
                for (int hf = 0; hf < 2; hf++)
                    mma16816h(s[np * 2 + hf], qf, kf[hf * 2], kf[hf * 2 + 1]);
            }
        }

        if (j >= 2 * qt) {
            const int rowA = qrow0 + wid * 16 + g;
            const int colBase = j * 64;
#pragma unroll
            for (int nt = 0; nt < 8; nt++) {
                const int col = colBase + nt * 8 + cA;
                if (col     > rowA)     s[nt][0] = -1e30f;
                if (col + 1 > rowA)     s[nt][1] = -1e30f;
                if (col     > rowA + 8) s[nt][2] = -1e30f;
                if (col + 1 > rowA + 8) s[nt][3] = -1e30f;
            }
        }

        float mxA = -1e30f, mxB = -1e30f;
#pragma unroll
        for (int nt = 0; nt < 8; nt++) {
            mxA = fmaxf(mxA, fmaxf(s[nt][0], s[nt][1]));
            mxB = fmaxf(mxB, fmaxf(s[nt][2], s[nt][3]));
        }
        mxA = fmaxf(mxA, __shfl_xor_sync(0xffffffffu, mxA, 1));
        mxA = fmaxf(mxA, __shfl_xor_sync(0xffffffffu, mxA, 2));
        mxB = fmaxf(mxB, __shfl_xor_sync(0xffffffffu, mxB, 1));
        mxB = fmaxf(mxB, __shfl_xor_sync(0xffffffffu, mxB, 2));
        const float mnA = fmaxf(mA, mxA), mnB = fmaxf(mB, mxB);
        const float alA = __expf(mA - mnA), alB = __expf(mB - mnB);

        uint32_t p[8][2];
        float rsA = 0.f, rsB = 0.f;
#pragma unroll
        for (int nt = 0; nt < 8; nt++) {
            float p0 = __expf(s[nt][0] - mnA);
            float p1 = __expf(s[nt][1] - mnA);
            float p2 = __expf(s[nt][2] - mnB);
            float p3 = __expf(s[nt][3] - mnB);
            rsA += p0 + p1;  rsB += p2 + p3;
            __half2 a0 = __floats2half2_rn(p0, p1);
            __half2 a1 = __floats2half2_rn(p2, p3);
            p[nt][0] = *reinterpret_cast<uint32_t*>(&a0);
            p[nt][1] = *reinterpret_cast<uint32_t*>(&a1);
        }
        rsA += __shfl_xor_sync(0xffffffffu, rsA, 1);
        rsA += __shfl_xor_sync(0xffffffffu, rsA, 2);
        rsB += __shfl_xor_sync(0xffffffffu, rsB, 1);
        rsB += __shfl_xor_sync(0xffffffffu, rsB, 2);
        lA = lA * alA + rsA;  mA = mnA;
        lB = lB * alB + rsB;  mB = mnB;

#pragma unroll
        for (int dt = 0; dt < 16; dt++) {
            o[dt][0] *= alA; o[dt][1] *= alA;
            o[dt][2] *= alB; o[dt][3] *= alB;
        }

#pragma unroll
        for (int kc = 0; kc < 4; kc++) {
            uint32_t a[4] = { p[2 * kc][0], p[2 * kc][1],
                              p[2 * kc + 1][0], p[2 * kc + 1][1] };
#pragma unroll
            for (int dp = 0; dp < 8; dp++) {
                uint32_t vf[4];
                const int rB = dp * 16 + ((lid >> 4) & 1) * 8 + (lid & 7);
                const int uB = kc * 2 + ((lid >> 3) & 1);
                ldsm_x4(vf, kb + AT_V + rB * 128 + ((uB ^ (rB & 7)) * 16));
#pragma unroll
                for (int hf = 0; hf < 2; hf++)
                    mma16816h(o[dp * 2 + hf], a, vf[hf * 2], vf[hf * 2 + 1]);
            }
        }
    }

    const float invA = 1.f / lA, invB = 1.f / lB;
    const int rowA = qrow0 + wid * 16 + g;
#pragma unroll
    for (int dt = 0; dt < 16; dt++) {
        const int d = h * HD + dt * 8 + cA;
        *(__half2*)&Yh[(size_t)rowA * DIM + d] =
            __floats2half2_rn(o[dt][0] * invA, o[dt][1] * invA);
        *(__half2*)&Yh[(size_t)(rowA + 8) * DIM + d] =
            __floats2half2_rn(o[dt][2] * invB, o[dt][3] * invB);
    }
}

// ---------------------------------------------------------------------------
// Launch
// ---------------------------------------------------------------------------
extern "C" void kernel_launch(void* const* d_in, const int* in_sizes, int n_in,
                              void* d_out, int out_size)
{
    const float* x  = (const float*)d_in[0];
    const float* fc = (const float*)d_in[1];
    const float* wq = (const float*)d_in[3];
    const float* wk = (const float*)d_in[4];
    const float* wv = (const float*)d_in[5];
    const float* wo = (const float*)d_in[6];
    float* out = (float*)d_out;

    float *Q, *Kp, *Vp;
    cudaGetSymbolAddress((void**)&Q,  g_q);
    cudaGetSymbolAddress((void**)&Kp, g_k);
    cudaGetSymbolAddress((void**)&Vp, g_v);

    __half *xh16, *xl16, *wq16, *wk16, *wv16, *wo16, *yh16, *q16, *k16, *vt16;
    cudaGetSymbolAddress((void**)&xh16, g_xh16);
    cudaGetSymbolAddress((void**)&xl16, g_xl16);
    cudaGetSymbolAddress((void**)&wq16, g_wq16);
    cudaGetSymbolAddress((void**)&wk16, g_wk16);
    cudaGetSymbolAddress((void**)&wv16, g_wv16);
    cudaGetSymbolAddress((void**)&wo16, g_wo16);
    cudaGetSymbolAddress((void**)&yh16, g_yh16);
    cudaGetSymbolAddress((void**)&q16,  g_q16);
    cudaGetSymbolAddress((void**)&k16,  g_k16);
    cudaGetSymbolAddress((void**)&vt16, g_vt16);

    cudaFuncSetAttribute(gemm_qkv16,
                         cudaFuncAttributeMaxDynamicSharedMemorySize, F2_SMEM);
    cudaFuncSetAttribute(gemm_f16_1p,
                         cudaFuncAttributeMaxDynamicSharedMemorySize, F1_SMEM);
    cudaFuncSetAttribute(attn_f16_kernel,
                         cudaFuncAttributeMaxDynamicSharedMemorySize, AT_SMEM);

    const int T = 256;
    split16_kernel<<<(SEQ * DIM / 8 + T - 1) / T, T>>>(x, xh16, xl16, SEQ * DIM / 8);
    trunc16_kernel<<<(DIM * DIM / 8 + T - 1) / T, T>>>(wq, wq16, DIM * DIM / 8);
    trunc16_kernel<<<(KVDIM * DIM / 8 + T - 1) / T, T>>>(wk, wk16, KVDIM * DIM / 8);
    trunc16_kernel<<<(KVDIM * DIM / 8 + T - 1) / T, T>>>(wv, wv16, KVDIM * DIM / 8);
    trunc16_kernel<<<(DIM * DIM / 8 + T - 1) / T, T>>>(wo, wo16, DIM * DIM / 8);

    // Fused QKV projection (fp16 2-pass)
    gemm_qkv16<<<dim3(24, SEQ / 128), 256, F2_SMEM>>>(
        xh16, xl16, wq16, wk16, wv16, Q, Kp, Vp);

    // RoPE -> fp16; V transpose -> fp16
    const float scale = 0.08838834764831845f;
    rope_f16_kernel<<<(SEQ * NH  * 64 + T - 1) / T, T>>>(
        Q,  fc, q16, NH,  scale, SEQ * NH  * 64);
    rope_f16_kernel<<<(SEQ * NKV * 64 + T - 1) / T, T>>>(
        Kp, fc, k16, NKV, 1.0f,  SEQ * NKV * 64);
    vt_f16_kernel<<<(KVDIM * SEQ + T - 1) / T, T>>>(Vp, vt16);

    // Attention (fp16 single-pass)
    attn_f16_kernel<<<dim3(SEQ / 128, NH), 256, AT_SMEM>>>(
        q16, k16, vt16, yh16);

    // Output projection (fp16 1-pass)
    gemm_f16_1p<<<dim3(DIM / 256, SEQ / 128), 256, F1_SMEM>>>(
        yh16, wo16, out, DIM);
}